// round 1
// baseline (speedup 1.0000x reference)
#include <cuda_runtime.h>
#include <math.h>

#define TPB   256
#define MT    128      // rows per block
#define DIN   512
#define HH    50
#define DOUT  128
#define KC    32
#define MAXN  0.996f   // (1 - 4e-3)/sqrt(c), c=1
#define MINN  1e-15f

// bias precompute results
__device__ float g_hb1[64];
__device__ float g_hb3[128];
__device__ float g_hb1sq;
__device__ float g_hb3sq;

__device__ __forceinline__ float artanh_c(float z) {
    z = fminf(z, 1.0f - 1e-7f);
    return 0.5f * logf((1.0f + z) / (1.0f - z));
}

// hyp_b = proj(expmap0(b, c), c); also store ||hyp_b||^2
__global__ void bias_kernel(const float* __restrict__ b1, const float* __restrict__ b3) {
    __shared__ float s[128];
    int t = threadIdx.x;

    float v1 = (t < HH) ? b1[t] : 0.0f;
    s[t] = v1 * v1;
    __syncthreads();
    for (int o = 64; o > 0; o >>= 1) { if (t < o) s[t] += s[t + o]; __syncthreads(); }
    float nb2 = s[0];
    __syncthreads();
    {
        float nb = fmaxf(sqrtf(nb2), MINN);
        float th = tanhf(nb);
        float sc = th / nb;
        if (th > MAXN) { sc *= MAXN / th; th = MAXN; }
        if (t < HH) g_hb1[t] = sc * v1;
        if (t == 0) g_hb1sq = th * th;
    }

    float v3 = b3[t];
    s[t] = v3 * v3;
    __syncthreads();
    for (int o = 64; o > 0; o >>= 1) { if (t < o) s[t] += s[t + o]; __syncthreads(); }
    nb2 = s[0];
    __syncthreads();
    {
        float nb = fmaxf(sqrtf(nb2), MINN);
        float th = tanhf(nb);
        float sc = th / nb;
        if (th > MAXN) { sc *= MAXN / th; th = MAXN; }
        g_hb3[t] = sc * v3;
        if (t == 0) g_hb3sq = th * th;
    }
}

// shared memory layout (floats):
//  W3s   : DOUT*HH        = 6400
//  xs_t  : KC*129         = 4128   (x chunk, transposed [k][row], stride 129)
//  W1s   : 56*KC          = 1792   (rows 50..55 zero)
//  us    : MT*57          = 7296   (u tile for GEMM2, stride 57)
//  red   : 8*256          = 2048
//  redout: 256
//  hb1s  : 64
//  hb3s  : 128
#define OFF_W3S   0
#define OFF_XS    6400
#define OFF_W1S   (6400 + 4128)
#define OFF_US    (OFF_W1S + 1792)
#define OFF_RED   (OFF_US + 7296)
#define OFF_RDO   (OFF_RED + 2048)
#define OFF_HB1   (OFF_RDO + 256)
#define OFF_HB3   (OFF_HB1 + 64)
#define SMEM_FLOATS (OFF_HB3 + 128)

extern __shared__ float sm[];

__global__ __launch_bounds__(TPB, 2) void hnn_kernel(
    const float* __restrict__ X,
    const float* __restrict__ W1,
    const float* __restrict__ W3,
    float* __restrict__ out,
    int N)
{
    float* W3s  = sm + OFF_W3S;
    float* xs   = sm + OFF_XS;    // [k][row], stride 129
    float* W1s  = sm + OFF_W1S;   // [h][k],  stride 32
    float* us   = sm + OFF_US;    // [row][h], stride 57
    float* red  = sm + OFF_RED;
    float* rdo  = sm + OFF_RDO;
    float* hb1s = sm + OFF_HB1;
    float* hb3s = sm + OFF_HB3;

    const int tid = threadIdx.x;
    const int m = tid & 31;       // lane
    const int c = tid >> 5;       // warp id 0..7 (column group)
    const int baseRow = blockIdx.x * MT;

    // resident loads: W3 (6400 floats, float4), biases, zero W1s pad rows
    {
        const float4* W3v = (const float4*)W3;
        for (int i = tid; i < (DOUT * HH) / 4; i += TPB)
            ((float4*)W3s)[i] = W3v[i];
        for (int i = tid; i < 64; i += TPB) hb1s[i] = (i < HH) ? g_hb1[i] : 0.0f;
        if (tid < DOUT) hb3s[tid] = g_hb3[tid];
        for (int i = 1600 + tid; i < 1792; i += TPB) W1s[i] = 0.0f;  // h=50..55 pad
    }
    const float hb1sq = g_hb1sq;
    const float hb3sq = g_hb3sq;

    // ---------------- Phase A: mx_raw = x @ W1^T, plus per-row sum(x^2) ----------------
    float acc[4][7];
    float x2p[4];
#pragma unroll
    for (int r = 0; r < 4; r++) {
        x2p[r] = 0.0f;
#pragma unroll
        for (int j = 0; j < 7; j++) acc[r][j] = 0.0f;
    }

    for (int kc = 0; kc < DIN / KC; kc++) {
        // load x chunk: 128 rows x 32 cols, transposed into xs[k][row]
#pragma unroll
        for (int p = 0; p < 4; p++) {
            int i = tid + TPB * p;           // 0..1023
            int row = i >> 3;                // 0..127
            int q = i & 7;                   // float4 index within 32 cols
            int gr = baseRow + row;
            float4 v = make_float4(0.f, 0.f, 0.f, 0.f);
            if (gr < N) v = *(const float4*)(X + (size_t)gr * DIN + kc * KC + q * 4);
            xs[(q * 4 + 0) * 129 + row] = v.x;
            xs[(q * 4 + 1) * 129 + row] = v.y;
            xs[(q * 4 + 2) * 129 + row] = v.z;
            xs[(q * 4 + 3) * 129 + row] = v.w;
        }
        // load W1 chunk: 50 rows x 32 cols (float4)
        for (int i = tid; i < 400; i += TPB) {
            int hh = i >> 3;
            int q = i & 7;
            float4 v = *(const float4*)(W1 + (size_t)hh * DIN + kc * KC + q * 4);
            *(float4*)(W1s + hh * 32 + q * 4) = v;
        }
        __syncthreads();

#pragma unroll 8
        for (int k = 0; k < KC; k++) {
            float xv[4];
#pragma unroll
            for (int r = 0; r < 4; r++) xv[r] = xs[k * 129 + (m + 32 * r)];
#pragma unroll
            for (int j = 0; j < 7; j++) {
                float w = W1s[(c * 7 + j) * 32 + k];
#pragma unroll
                for (int r = 0; r < 4; r++) acc[r][j] = fmaf(xv[r], w, acc[r][j]);
            }
        }
        // x^2 partial: warp c owns local k = 4c..4c+3 (dedup across warps)
#pragma unroll
        for (int kk = 0; kk < 4; kk++) {
            int k = c * 4 + kk;
#pragma unroll
            for (int r = 0; r < 4; r++) {
                float xv = xs[k * 129 + (m + 32 * r)];
                x2p[r] = fmaf(xv, xv, x2p[r]);
            }
        }
        __syncthreads();
    }

    // ---- Reduce R1: sum(x^2) per row ----
#pragma unroll
    for (int r = 0; r < 4; r++) red[c * 256 + (m + 32 * r)] = x2p[r];
    __syncthreads();
    if (tid < 128) {
        float s = 0.0f;
#pragma unroll
        for (int cc = 0; cc < 8; cc++) s += red[cc * 256 + tid];
        rdo[tid] = s;
    }
    __syncthreads();

    // expmap0 scale + xn for linear1
    float al[4], xn1[4];
#pragma unroll
    for (int r = 0; r < 4; r++) {
        float nx = fmaxf(sqrtf(rdo[m + 32 * r]), MINN);
        float th = tanhf(nx);
        al[r] = th / nx;                 // h = al * x
        xn1[r] = fmaxf(th, MINN);        // ||h||
    }

    // ---- R2: sum(mx^2) and sum(mx*hb1); acc <- mx = al * raw ----
#pragma unroll
    for (int r = 0; r < 4; r++) {
        float p0 = 0.0f, p1 = 0.0f;
#pragma unroll
        for (int j = 0; j < 7; j++) {
            float v = al[r] * acc[r][j];   // h>=50: acc=0 (W1s pad) -> v=0
            acc[r][j] = v;
            p0 = fmaf(v, v, p0);
            p1 = fmaf(v, hb1s[c * 7 + j], p1);  // hb1s pad = 0
        }
        red[c * 256 + (m + 32 * r)] = p0;
        red[c * 256 + 128 + (m + 32 * r)] = p1;
    }
    __syncthreads();
    {
        float s = 0.0f;
#pragma unroll
        for (int cc = 0; cc < 8; cc++) s += red[cc * 256 + tid];
        rdo[tid] = s;
    }
    __syncthreads();

    // ---- Epilogue 1: mobius_matvec tail + proj + mobius_add(hb1) + proj + logmap0 ----
    float C1[4], C2[4], un[4];
#pragma unroll
    for (int r = 0; r < 4; r++) {
        int row = m + 32 * r;
        float mxn2 = rdo[row];
        float dotb = rdo[128 + row];
        float mxn = fmaxf(sqrtf(mxn2), MINN);
        float art = artanh_c(xn1[r]);
        float t = tanhf(mxn / xn1[r] * art);
        float g = t / mxn;                       // res = g * mx
        float rn = t;
        if (rn > MAXN) { g *= MAXN / rn; rn = MAXN; }   // proj(res)
        float xy = g * dotb;
        float x2 = rn * rn;
        float den = fmaxf(1.0f + 2.0f * xy + x2 * hb1sq, MINN);
        float A = (1.0f + 2.0f * xy + hb1sq) / den;
        float B = (1.0f - x2) / den;
        float nv2 = A * A * x2 + 2.0f * A * B * xy + B * B * hb1sq;
        float nv = sqrtf(nv2);
        float pf = (nv > MAXN) ? (MAXN / nv) : 1.0f;    // proj(v)
        nv = fminf(nv, MAXN);
        float beta = artanh_c(nv) / fmaxf(nv, MINN);    // logmap0 scale
        C1[r] = beta * pf * A * g;   // coefficient on mx
        C2[r] = beta * pf * B;       // coefficient on hb1
    }

    // ---- LeakyReLU (elementwise) + R3: sum(xt^2) ----
#pragma unroll
    for (int r = 0; r < 4; r++) {
        float p = 0.0f;
#pragma unroll
        for (int j = 0; j < 7; j++) {
            float xt = C1[r] * acc[r][j] + C2[r] * hb1s[c * 7 + j];  // pad cols -> 0
            xt = (xt > 0.0f) ? xt : 0.01f * xt;
            acc[r][j] = xt;
            p = fmaf(xt, xt, p);
        }
        red[c * 256 + (m + 32 * r)] = p;
    }
    __syncthreads();
    if (tid < 128) {
        float s = 0.0f;
#pragma unroll
        for (int cc = 0; cc < 8; cc++) s += red[cc * 256 + tid];
        rdo[tid] = s;
    }
    __syncthreads();

    // expmap0(xt) + proj -> u, write u tile to smem; un = ||u||
#pragma unroll
    for (int r = 0; r < 4; r++) {
        int row = m + 32 * r;
        float nxt = fmaxf(sqrtf(rdo[row]), MINN);
        float th = tanhf(nxt);
        float gam = th / nxt;
        if (th > MAXN) { gam *= MAXN / th; th = MAXN; }
        un[r] = fmaxf(th, MINN);
#pragma unroll
        for (int j = 0; j < 7; j++)
            us[row * 57 + c * 7 + j] = gam * acc[r][j];
    }
    __syncthreads();

    // ---------------- Phase B: mx2 = u @ W3^T ----------------
    float acc2[4][16];
#pragma unroll
    for (int r = 0; r < 4; r++)
#pragma unroll
        for (int j = 0; j < 16; j++) acc2[r][j] = 0.0f;

#pragma unroll 2
    for (int k = 0; k < HH; k++) {
        float uv[4];
#pragma unroll
        for (int r = 0; r < 4; r++) uv[r] = us[(m + 32 * r) * 57 + k];
#pragma unroll
        for (int j = 0; j < 16; j++) {
            float w = W3s[(c * 16 + j) * HH + k];
#pragma unroll
            for (int r = 0; r < 4; r++) acc2[r][j] = fmaf(uv[r], w, acc2[r][j]);
        }
    }

    // ---- R4: sum(mx2^2), sum(mx2*hb3) ----
#pragma unroll
    for (int r = 0; r < 4; r++) {
        float p0 = 0.0f, p1 = 0.0f;
#pragma unroll
        for (int j = 0; j < 16; j++) {
            float v = acc2[r][j];
            p0 = fmaf(v, v, p0);
            p1 = fmaf(v, hb3s[c * 16 + j], p1);
        }
        red[c * 256 + (m + 32 * r)] = p0;
        red[c * 256 + 128 + (m + 32 * r)] = p1;
    }
    __syncthreads();
    {
        float s = 0.0f;
#pragma unroll
        for (int cc = 0; cc < 8; cc++) s += red[cc * 256 + tid];
        rdo[tid] = s;
    }
    __syncthreads();

    // ---- Epilogue 2 + store ----
#pragma unroll
    for (int r = 0; r < 4; r++) {
        int row = m + 32 * r;
        int grow = baseRow + row;
        float mxn2 = rdo[row];
        float dotb = rdo[128 + row];
        float mxn = fmaxf(sqrtf(mxn2), MINN);
        float art = artanh_c(un[r]);
        float t = tanhf(mxn / un[r] * art);
        float g = t / mxn;
        float rn = t;
        if (rn > MAXN) { g *= MAXN / rn; rn = MAXN; }
        float xy = g * dotb;
        float x2 = rn * rn;
        float den = fmaxf(1.0f + 2.0f * xy + x2 * hb3sq, MINN);
        float A = (1.0f + 2.0f * xy + hb3sq) / den;
        float B = (1.0f - x2) / den;
        float nv2 = A * A * x2 + 2.0f * A * B * xy + B * B * hb3sq;
        float nv = sqrtf(nv2);
        float pf = (nv > MAXN) ? (MAXN / nv) : 1.0f;
        float cA = pf * A * g;
        float cB = pf * B;
        if (grow < N) {
            float* orow = out + (size_t)grow * DOUT + c * 16;
#pragma unroll
            for (int q = 0; q < 4; q++) {
                float4 v;
                v.x = cA * acc2[r][q * 4 + 0] + cB * hb3s[c * 16 + q * 4 + 0];
                v.y = cA * acc2[r][q * 4 + 1] + cB * hb3s[c * 16 + q * 4 + 1];
                v.z = cA * acc2[r][q * 4 + 2] + cB * hb3s[c * 16 + q * 4 + 2];
                v.w = cA * acc2[r][q * 4 + 3] + cB * hb3s[c * 16 + q * 4 + 3];
                *(float4*)(orow + q * 4) = v;
            }
        }
    }
}

extern "C" void kernel_launch(void* const* d_in, const int* in_sizes, int n_in,
                              void* d_out, int out_size) {
    const float* x  = (const float*)d_in[0];
    const float* W1 = (const float*)d_in[1];
    const float* b1 = (const float*)d_in[2];
    const float* W3 = (const float*)d_in[3];
    const float* b3 = (const float*)d_in[4];
    float* out = (float*)d_out;
    int N = in_sizes[0] / DIN;

    size_t smem = SMEM_FLOATS * sizeof(float);
    cudaFuncSetAttribute(hnn_kernel, cudaFuncAttributeMaxDynamicSharedMemorySize, (int)smem);

    bias_kernel<<<1, 128>>>(b1, b3);
    hnn_kernel<<<(N + MT - 1) / MT, TPB, smem>>>(x, W1, W3, out, N);
}

// round 2
// speedup vs baseline: 1.0699x; 1.0699x over previous
#include <cuda_runtime.h>
#include <math.h>

#define TPB   256
#define MT    128      // rows per block
#define DIN   512
#define HH    50
#define DOUT  128
#define MAXN  0.996f   // (1 - 4e-3)/sqrt(c), c=1
#define MINN  1e-15f

typedef unsigned long long ull;

// bias precompute results
__device__ float g_hb1[64];
__device__ float g_hb3[128];
__device__ float g_hb1sq;
__device__ float g_hb3sq;

__device__ __forceinline__ float artanh_c(float z) {
    z = fminf(z, 1.0f - 1e-7f);
    return 0.5f * logf((1.0f + z) / (1.0f - z));
}

__device__ __forceinline__ ull ffma2(ull a, ull b, ull c) {
    ull d;
    asm("fma.rn.f32x2 %0, %1, %2, %3;" : "=l"(d) : "l"(a), "l"(b), "l"(c));
    return d;
}
__device__ __forceinline__ ull dup2(float x) {
    ull d;
    asm("mov.b64 %0, {%1, %1};" : "=l"(d) : "f"(x));
    return d;
}
__device__ __forceinline__ float sum2(ull p) {
    float lo, hi;
    asm("mov.b64 {%0, %1}, %2;" : "=f"(lo), "=f"(hi) : "l"(p));
    return lo + hi;
}
__device__ __forceinline__ void unpack2(ull p, float& lo, float& hi) {
    asm("mov.b64 {%0, %1}, %2;" : "=f"(lo), "=f"(hi) : "l"(p));
}

union F4U { float4 f4; ull u[2]; };

// hyp_b = proj(expmap0(b, c), c); also store ||hyp_b||^2
__global__ void bias_kernel(const float* __restrict__ b1, const float* __restrict__ b3) {
    __shared__ float s[128];
    int t = threadIdx.x;

    float v1 = (t < HH) ? b1[t] : 0.0f;
    s[t] = v1 * v1;
    __syncthreads();
    for (int o = 64; o > 0; o >>= 1) { if (t < o) s[t] += s[t + o]; __syncthreads(); }
    float nb2 = s[0];
    __syncthreads();
    {
        float nb = fmaxf(sqrtf(nb2), MINN);
        float th = tanhf(nb);
        float sc = th / nb;
        if (th > MAXN) { sc *= MAXN / th; th = MAXN; }
        if (t < HH) g_hb1[t] = sc * v1;
        if (t == 0) g_hb1sq = th * th;
    }

    float v3 = b3[t];
    s[t] = v3 * v3;
    __syncthreads();
    for (int o = 64; o > 0; o >>= 1) { if (t < o) s[t] += s[t + o]; __syncthreads(); }
    nb2 = s[0];
    __syncthreads();
    {
        float nb = fmaxf(sqrtf(nb2), MINN);
        float th = tanhf(nb);
        float sc = th / nb;
        if (th > MAXN) { sc *= MAXN / th; th = MAXN; }
        g_hb3[t] = sc * v3;
        if (t == 0) g_hb3sq = th * th;
    }
}

// shared memory layout (floats):
//  W3t   : HH*DOUT (transposed [k][j])       = 6400
//  xs    : MT*36  ([row][k] stride 36)       = 4608
//  W1s   : 56*32  ([h][k], rows 50..55 zero) = 1792
//  us    : MT*57  ([row][k] stride 57)       = 7296
//  red   : 2048
//  rdo   : 256
//  hb1s  : 64
//  hb3s  : 128
#define OFF_W3T   0
#define OFF_XS    6400
#define OFF_W1S   (OFF_XS + 4608)
#define OFF_US    (OFF_W1S + 1792)
#define OFF_RED   (OFF_US + 7296)
#define OFF_RDO   (OFF_RED + 2048)
#define OFF_HB1   (OFF_RDO + 256)
#define OFF_HB3   (OFF_HB1 + 64)
#define SMEM_FLOATS (OFF_HB3 + 128)

extern __shared__ float sm[];

__global__ __launch_bounds__(TPB, 2) void hnn_kernel(
    const float* __restrict__ X,
    const float* __restrict__ W1,
    const float* __restrict__ W3,
    float* __restrict__ out,
    int N)
{
    float* W3t  = sm + OFF_W3T;   // [k][j], stride 128
    float* xs   = sm + OFF_XS;    // [row][k], stride 36
    float* W1s  = sm + OFF_W1S;   // [h][k], stride 32
    float* us   = sm + OFF_US;    // [row][k], stride 57
    float* red  = sm + OFF_RED;
    float* rdo  = sm + OFF_RDO;
    float* hb1s = sm + OFF_HB1;
    float* hb3s = sm + OFF_HB3;

    const int tid = threadIdx.x;
    const int m = tid & 31;       // lane
    const int c = tid >> 5;       // warp id 0..7 (column group)
    const int baseRow = blockIdx.x * MT;

    // resident loads: W3 transposed into W3t[k][j], biases, zero W1s pad rows
    {
        for (int i = tid; i < DOUT * HH; i += TPB) {
            int j = i / HH;
            int k = i - j * HH;
            W3t[k * 128 + j] = W3[i];
        }
        for (int i = tid; i < 64; i += TPB) hb1s[i] = (i < HH) ? g_hb1[i] : 0.0f;
        if (tid < DOUT) hb3s[tid] = g_hb3[tid];
        for (int i = 1600 + tid; i < 1792; i += TPB) W1s[i] = 0.0f;  // h=50..55 pad
    }
    const float hb1sq = g_hb1sq;
    const float hb3sq = g_hb3sq;

    // ---------------- Phase A: mx_raw = x @ W1^T (f32x2, packed along k) ----------------
    ull acc[4][7];
    float x2acc[4];
#pragma unroll
    for (int r = 0; r < 4; r++) {
        x2acc[r] = 0.0f;
#pragma unroll
        for (int j = 0; j < 7; j++) acc[r][j] = 0ull;
    }

    for (int kc = 0; kc < DIN / 32; kc++) {
        // load x chunk [128 rows x 32 k] row-major into xs; fold in sum(x^2)
#pragma unroll
        for (int p = 0; p < 4; p++) {
            int i = tid + TPB * p;           // 0..1023
            int row = i >> 3;                // 0..127
            int q = i & 7;
            int gr = baseRow + row;
            float4 v = make_float4(0.f, 0.f, 0.f, 0.f);
            if (gr < N) v = *(const float4*)(X + (size_t)gr * DIN + kc * 32 + q * 4);
            *(float4*)(xs + row * 36 + q * 4) = v;
            x2acc[p] = fmaf(v.x, v.x, fmaf(v.y, v.y, fmaf(v.z, v.z, fmaf(v.w, v.w, x2acc[p]))));
        }
        // load W1 chunk: 50 rows x 32 cols (float4)
        for (int i = tid; i < 400; i += TPB) {
            int hh = i >> 3;
            int q = i & 7;
            *(float4*)(W1s + hh * 32 + q * 4) = *(const float4*)(W1 + (size_t)hh * DIN + kc * 32 + q * 4);
        }
        __syncthreads();

#pragma unroll
        for (int q = 0; q < 8; q++) {
            F4U w[7], xv[4];
#pragma unroll
            for (int j = 0; j < 7; j++) w[j].f4 = *(float4*)(W1s + (c * 7 + j) * 32 + q * 4);
#pragma unroll
            for (int r = 0; r < 4; r++) xv[r].f4 = *(float4*)(xs + (m + 32 * r) * 36 + q * 4);
#pragma unroll
            for (int j = 0; j < 7; j++)
#pragma unroll
                for (int r = 0; r < 4; r++) {
                    acc[r][j] = ffma2(xv[r].u[0], w[j].u[0], acc[r][j]);
                    acc[r][j] = ffma2(xv[r].u[1], w[j].u[1], acc[r][j]);
                }
        }
        __syncthreads();
    }

    // ---- Reduce R1: sum(x^2) per row (x2acc[p] is partial for row tid>>3 + 32p, q=tid&7) ----
#pragma unroll
    for (int p = 0; p < 4; p++)
        red[((tid >> 3) + 32 * p) * 8 + (tid & 7)] = x2acc[p];
    __syncthreads();
    if (tid < 128) {
        float4 a = *(float4*)(red + tid * 8);
        float4 b = *(float4*)(red + tid * 8 + 4);
        rdo[tid] = (a.x + a.y) + (a.z + a.w) + (b.x + b.y) + (b.z + b.w);
    }
    __syncthreads();

    // expmap0 scale + xn for linear1
    float al[4], xn1[4];
#pragma unroll
    for (int r = 0; r < 4; r++) {
        float nx = fmaxf(sqrtf(rdo[m + 32 * r]), MINN);
        float th = tanhf(nx);
        al[r] = th / nx;                 // h = al * x
        xn1[r] = fmaxf(th, MINN);        // ||h||
    }

    // collapse packed accumulators to scalar mx = al * (lo+hi)
    float mx[4][7];
#pragma unroll
    for (int r = 0; r < 4; r++)
#pragma unroll
        for (int j = 0; j < 7; j++)
            mx[r][j] = al[r] * sum2(acc[r][j]);

    // ---- R2: sum(mx^2) and sum(mx*hb1) ----
#pragma unroll
    for (int r = 0; r < 4; r++) {
        float p0 = 0.0f, p1 = 0.0f;
#pragma unroll
        for (int j = 0; j < 7; j++) {
            float v = mx[r][j];            // cols >= 50 are 0 (W1s pad)
            p0 = fmaf(v, v, p0);
            p1 = fmaf(v, hb1s[c * 7 + j], p1);
        }
        red[c * 256 + (m + 32 * r)] = p0;
        red[c * 256 + 128 + (m + 32 * r)] = p1;
    }
    __syncthreads();
    {
        float s = 0.0f;
#pragma unroll
        for (int cc = 0; cc < 8; cc++) s += red[cc * 256 + tid];
        rdo[tid] = s;
    }
    __syncthreads();

    // ---- Epilogue 1: mobius_matvec tail + proj + mobius_add(hb1) + proj + logmap0 ----
    float C1[4], C2[4], un[4];
#pragma unroll
    for (int r = 0; r < 4; r++) {
        int row = m + 32 * r;
        float mxn2 = rdo[row];
        float dotb = rdo[128 + row];
        float mxn = fmaxf(sqrtf(mxn2), MINN);
        float art = artanh_c(xn1[r]);
        float t = tanhf(mxn / xn1[r] * art);
        float g = t / mxn;                       // res = g * mx
        float rn = t;
        if (rn > MAXN) { g *= MAXN / rn; rn = MAXN; }   // proj(res)
        float xy = g * dotb;
        float x2 = rn * rn;
        float den = fmaxf(1.0f + 2.0f * xy + x2 * hb1sq, MINN);
        float A = (1.0f + 2.0f * xy + hb1sq) / den;
        float B = (1.0f - x2) / den;
        float nv2 = A * A * x2 + 2.0f * A * B * xy + B * B * hb1sq;
        float nv = sqrtf(nv2);
        float pf = (nv > MAXN) ? (MAXN / nv) : 1.0f;    // proj(v)
        nv = fminf(nv, MAXN);
        float beta = artanh_c(nv) / fmaxf(nv, MINN);    // logmap0 scale
        C1[r] = beta * pf * A * g;   // coefficient on mx
        C2[r] = beta * pf * B;       // coefficient on hb1
    }

    // ---- LeakyReLU (elementwise) + R3: sum(xt^2) ----
#pragma unroll
    for (int r = 0; r < 4; r++) {
        float p = 0.0f;
#pragma unroll
        for (int j = 0; j < 7; j++) {
            float xt = C1[r] * mx[r][j] + C2[r] * hb1s[c * 7 + j];  // pad cols -> 0
            xt = (xt > 0.0f) ? xt : 0.01f * xt;
            mx[r][j] = xt;
            p = fmaf(xt, xt, p);
        }
        red[c * 256 + (m + 32 * r)] = p;
    }
    __syncthreads();
    if (tid < 128) {
        float s = 0.0f;
#pragma unroll
        for (int cc = 0; cc < 8; cc++) s += red[cc * 256 + tid];
        rdo[tid] = s;
    }
    __syncthreads();

    // expmap0(xt) + proj -> u, write u tile to smem; un = ||u||
#pragma unroll
    for (int r = 0; r < 4; r++) {
        int row = m + 32 * r;
        float nxt = fmaxf(sqrtf(rdo[row]), MINN);
        float th = tanhf(nxt);
        float gam = th / nxt;
        if (th > MAXN) { gam *= MAXN / th; th = MAXN; }
        un[r] = fmaxf(th, MINN);
#pragma unroll
        for (int j = 0; j < 7; j++)
            us[row * 57 + c * 7 + j] = gam * mx[r][j];
    }
    __syncthreads();

    // ---------------- Phase B: mx2 = u @ W3^T (f32x2, packed along j) ----------------
    // acc2[r][jj] holds cols (c*16 + 2jj, c*16 + 2jj + 1)
    ull acc2[4][8];
#pragma unroll
    for (int r = 0; r < 4; r++)
#pragma unroll
        for (int jj = 0; jj < 8; jj++) acc2[r][jj] = 0ull;

#pragma unroll 2
    for (int k = 0; k < HH; k++) {
        ull uvp[4];
#pragma unroll
        for (int r = 0; r < 4; r++) uvp[r] = dup2(us[(m + 32 * r) * 57 + k]);
        ull w[8];
#pragma unroll
        for (int jj = 0; jj < 8; jj++) w[jj] = *(ull*)(W3t + k * 128 + c * 16 + jj * 2);
#pragma unroll
        for (int jj = 0; jj < 8; jj++)
#pragma unroll
            for (int r = 0; r < 4; r++)
                acc2[r][jj] = ffma2(uvp[r], w[jj], acc2[r][jj]);
    }

    // ---- R4: sum(mx2^2), sum(mx2*hb3) (packed) ----
#pragma unroll
    for (int r = 0; r < 4; r++) {
        ull p0 = 0ull, p1 = 0ull;
#pragma unroll
        for (int jj = 0; jj < 8; jj++) {
            ull hb = *(ull*)(hb3s + c * 16 + jj * 2);
            p0 = ffma2(acc2[r][jj], acc2[r][jj], p0);
            p1 = ffma2(acc2[r][jj], hb, p1);
        }
        red[c * 256 + (m + 32 * r)] = sum2(p0);
        red[c * 256 + 128 + (m + 32 * r)] = sum2(p1);
    }
    __syncthreads();
    {
        float s = 0.0f;
#pragma unroll
        for (int cc = 0; cc < 8; cc++) s += red[cc * 256 + tid];
        rdo[tid] = s;
    }
    __syncthreads();

    // ---- Epilogue 2 + store ----
#pragma unroll
    for (int r = 0; r < 4; r++) {
        int row = m + 32 * r;
        int grow = baseRow + row;
        float mxn2 = rdo[row];
        float dotb = rdo[128 + row];
        float mxn = fmaxf(sqrtf(mxn2), MINN);
        float art = artanh_c(un[r]);
        float t = tanhf(mxn / un[r] * art);
        float g = t / mxn;
        float rn = t;
        if (rn > MAXN) { g *= MAXN / rn; rn = MAXN; }
        float xy = g * dotb;
        float x2 = rn * rn;
        float den = fmaxf(1.0f + 2.0f * xy + x2 * hb3sq, MINN);
        float A = (1.0f + 2.0f * xy + hb3sq) / den;
        float B = (1.0f - x2) / den;
        float nv2 = A * A * x2 + 2.0f * A * B * xy + B * B * hb3sq;
        float nv = sqrtf(nv2);
        float pf = (nv > MAXN) ? (MAXN / nv) : 1.0f;
        float cA = pf * A * g;
        float cB = pf * B;
        if (grow < N) {
            float* orow = out + (size_t)grow * DOUT + c * 16;
#pragma unroll
            for (int q = 0; q < 4; q++) {
                float l0, h0, l1, h1;
                unpack2(acc2[r][q * 2], l0, h0);
                unpack2(acc2[r][q * 2 + 1], l1, h1);
                float4 v;
                v.x = cA * l0 + cB * hb3s[c * 16 + q * 4 + 0];
                v.y = cA * h0 + cB * hb3s[c * 16 + q * 4 + 1];
                v.z = cA * l1 + cB * hb3s[c * 16 + q * 4 + 2];
                v.w = cA * h1 + cB * hb3s[c * 16 + q * 4 + 3];
                *(float4*)(orow + q * 4) = v;
            }
        }
    }
}

extern "C" void kernel_launch(void* const* d_in, const int* in_sizes, int n_in,
                              void* d_out, int out_size) {
    const float* x  = (const float*)d_in[0];
    const float* W1 = (const float*)d_in[1];
    const float* b1 = (const float*)d_in[2];
    const float* W3 = (const float*)d_in[3];
    const float* b3 = (const float*)d_in[4];
    float* out = (float*)d_out;
    int N = in_sizes[0] / DIN;

    size_t smem = SMEM_FLOATS * sizeof(float);
    cudaFuncSetAttribute(hnn_kernel, cudaFuncAttributeMaxDynamicSharedMemorySize, (int)smem);

    bias_kernel<<<1, 128>>>(b1, b3);
    hnn_kernel<<<(N + MT - 1) / MT, TPB, smem>>>(x, W1, W3, out, N);
}

// round 4
// speedup vs baseline: 1.2855x; 1.2016x over previous
#include <cuda_runtime.h>
#include <cuda_bf16.h>
#include <math.h>
#include <stdint.h>

#define TPB   256
#define MT    128
#define DIN   512
#define HH    50
#define DOUT  128
#define MAXN  0.996f
#define MINN  1e-15f

typedef unsigned long long ull;
typedef uint32_t u32;

// ---- smem byte offsets ----
#define OFF_XH   0          // 128 rows * 144B (64 bf16 + pad)
#define OFF_XL   18432
#define OFF_W1H  36864      // 64 rows * 144B (rows 50..63 zero)
#define OFF_W1L  46080
#define OFF_MXS  0          // alias over XH/XL: 128 * 65 f32 = 33280B
#define OFF_W3T  55296      // 6400 f32
#define OFF_RED  80896      // 2048 f32
#define OFF_RDO  89088      // 256 f32
#define OFF_HB1  90112      // 64 f32
#define OFF_HB3  90368      // 128 f32
#define OFF_UNS  90880      // 128 f32
#define OFF_X2S  91392      // 256 f32
#define SMEM_BYTES 92416

__device__ float g_hb1[64];
__device__ float g_hb3[128];
__device__ float g_hb1sq, g_hb3sq;

__device__ __forceinline__ float artanh_c(float z) {
    z = fminf(z, 1.0f - 1e-7f);
    return 0.5f * logf((1.0f + z) / (1.0f - z));
}

// ---- f32x2 helpers (GEMM2) ----
__device__ __forceinline__ ull ffma2(ull a, ull b, ull c) {
    ull d; asm("fma.rn.f32x2 %0, %1, %2, %3;" : "=l"(d) : "l"(a), "l"(b), "l"(c)); return d;
}
__device__ __forceinline__ ull dup2(float x) {
    ull d; asm("mov.b64 %0, {%1, %1};" : "=l"(d) : "f"(x)); return d;
}
__device__ __forceinline__ float sum2(ull p) {
    float lo, hi; asm("mov.b64 {%0, %1}, %2;" : "=f"(lo), "=f"(hi) : "l"(p)); return lo + hi;
}
__device__ __forceinline__ void unpack2(ull p, float& lo, float& hi) {
    asm("mov.b64 {%0, %1}, %2;" : "=f"(lo), "=f"(hi) : "l"(p));
}

// ---- HMMA helpers ----
__device__ __forceinline__ void mma_bf16(float* d, const u32* a, const u32* b) {
    asm("mma.sync.aligned.m16n8k16.row.col.f32.bf16.bf16.f32 "
        "{%0,%1,%2,%3}, {%4,%5,%6,%7}, {%8,%9}, {%0,%1,%2,%3};"
        : "+f"(d[0]), "+f"(d[1]), "+f"(d[2]), "+f"(d[3])
        : "r"(a[0]), "r"(a[1]), "r"(a[2]), "r"(a[3]), "r"(b[0]), "r"(b[1]));
}
__device__ __forceinline__ void ldsm4(u32* r, u32 addr) {
    asm volatile("ldmatrix.sync.aligned.m8n8.x4.shared.b16 {%0,%1,%2,%3}, [%4];"
        : "=r"(r[0]), "=r"(r[1]), "=r"(r[2]), "=r"(r[3]) : "r"(addr));
}
__device__ __forceinline__ u32 packh(__nv_bfloat16 a, __nv_bfloat16 b) {
    __nv_bfloat162 t = __halves2bfloat162(a, b);
    return *reinterpret_cast<u32*>(&t);
}

// hyp_b = proj(expmap0(b)); also ||hyp_b||^2
__global__ void bias_kernel(const float* __restrict__ b1, const float* __restrict__ b3) {
    __shared__ float s[128];
    int t = threadIdx.x;

    float v1 = (t < HH) ? b1[t] : 0.0f;
    s[t] = v1 * v1;
    __syncthreads();
    for (int o = 64; o > 0; o >>= 1) { if (t < o) s[t] += s[t + o]; __syncthreads(); }
    float nb2 = s[0];
    __syncthreads();
    {
        float nb = fmaxf(sqrtf(nb2), MINN);
        float th = tanhf(nb);
        float sc = th / nb;
        if (th > MAXN) { sc *= MAXN / th; th = MAXN; }
        if (t < HH) g_hb1[t] = sc * v1;
        if (t == 0) g_hb1sq = th * th;
    }

    float v3 = b3[t];
    s[t] = v3 * v3;
    __syncthreads();
    for (int o = 64; o > 0; o >>= 1) { if (t < o) s[t] += s[t + o]; __syncthreads(); }
    nb2 = s[0];
    __syncthreads();
    {
        float nb = fmaxf(sqrtf(nb2), MINN);
        float th = tanhf(nb);
        float sc = th / nb;
        if (th > MAXN) { sc *= MAXN / th; th = MAXN; }
        g_hb3[t] = sc * v3;
        if (t == 0) g_hb3sq = th * th;
    }
}

extern __shared__ __align__(1024) char smraw[];

__global__ __launch_bounds__(TPB, 2)
void hnn_kernel(const float* __restrict__ X, const float* __restrict__ W1,
                const float* __restrict__ W3, float* __restrict__ out, int N)
{
    const u32 sb = (u32)__cvta_generic_to_shared(smraw);
    float* mxs  = (float*)(smraw + OFF_MXS);   // [row][j], stride 65
    float* W3t  = (float*)(smraw + OFF_W3T);   // [k][j], stride 128
    float* red  = (float*)(smraw + OFF_RED);
    float* rdo  = (float*)(smraw + OFF_RDO);
    float* hb1s = (float*)(smraw + OFF_HB1);
    float* hb3s = (float*)(smraw + OFF_HB3);
    float* un_s = (float*)(smraw + OFF_UNS);
    float* x2s  = (float*)(smraw + OFF_X2S);

    const int tid = threadIdx.x;
    const int lane = tid & 31;
    const int c = tid >> 5;           // warp id
    const int mg = c & 3;             // row group (32 rows)
    const int ng = c >> 2;            // col group (32 cols)
    const int baseRow = blockIdx.x * MT;

    // init: zero W1 smem pad rows (50..63 never rewritten), load W3t, biases
    for (int i = tid; i < 18432 / 16; i += TPB)
        *(float4*)(smraw + OFF_W1H + i * 16) = make_float4(0.f, 0.f, 0.f, 0.f);
    for (int i = tid; i < DOUT * HH; i += TPB) {
        int j = i / HH, k = i - j * HH;
        W3t[k * 128 + j] = W3[i];
    }
    for (int i = tid; i < 64; i += TPB) hb1s[i] = (i < HH) ? g_hb1[i] : 0.0f;
    if (tid < DOUT) hb3s[tid] = g_hb3[tid];
    const float hb1sq = g_hb1sq;
    const float hb3sq = g_hb3sq;
    __syncthreads();

    // ---------------- GEMM1: mx_raw = x @ W1^T  (HMMA bf16, 3-way split) ----------------
    const int xrow = tid & 127;
    const int xkh  = tid >> 7;        // which 32-k half this thread loads
    const int gr = baseRow + xrow;
    const bool valid = gr < N;
    const float* xptr = X + (size_t)gr * DIN + xkh * 32;
    float x2a = 0.0f;

    float acc[2][4][4];
#pragma unroll
    for (int mt = 0; mt < 2; mt++)
#pragma unroll
        for (int nt = 0; nt < 4; nt++)
#pragma unroll
            for (int e = 0; e < 4; e++) acc[mt][nt][e] = 0.0f;

    // precompute ldmatrix lane addresses (offsets within tile)
    const u32 aRow = (u32)(mg * 32 + (lane & 15));     // + mt*16
    const u32 aKof = (u32)((lane >> 4) * 16);          // + k16*32
    const u32 bN   = (u32)(ng * 32 + ((lane >> 4) * 8) + (lane & 7));  // + np*16
    const u32 bKof = (u32)(((lane >> 3) & 1) * 16);    // + k16*32

    for (int kc = 0; kc < 8; kc++) {
        // -- x chunk: 128 rows x 64 k, f32 -> bf16 hi/lo --
#pragma unroll
        for (int q = 0; q < 8; q++) {
            float4 v = make_float4(0.f, 0.f, 0.f, 0.f);
            if (valid) v = *(const float4*)(xptr + kc * 64 + q * 4);
            __nv_bfloat16 h0 = __float2bfloat16(v.x), h1 = __float2bfloat16(v.y);
            __nv_bfloat16 h2 = __float2bfloat16(v.z), h3 = __float2bfloat16(v.w);
            float l0 = v.x - __bfloat162float(h0), l1 = v.y - __bfloat162float(h1);
            float l2 = v.z - __bfloat162float(h2), l3 = v.w - __bfloat162float(h3);
            ull hp = (ull)packh(h0, h1) | ((ull)packh(h2, h3) << 32);
            ull lp = (ull)packh(__float2bfloat16(l0), __float2bfloat16(l1))
                   | ((ull)packh(__float2bfloat16(l2), __float2bfloat16(l3)) << 32);
            u32 off = (u32)(xrow * 144 + xkh * 64 + q * 8);
            *(ull*)(smraw + OFF_XH + off) = hp;
            *(ull*)(smraw + OFF_XL + off) = lp;
            x2a = fmaf(v.x, v.x, fmaf(v.y, v.y, fmaf(v.z, v.z, fmaf(v.w, v.w, x2a))));
        }
        // -- W1 chunk: 50 rows x 64 k --
        for (int i = tid; i < 800; i += TPB) {
            int n = i >> 4, k4 = i & 15;
            float4 wv = *(const float4*)(W1 + (size_t)n * DIN + kc * 64 + k4 * 4);
            __nv_bfloat16 h0 = __float2bfloat16(wv.x), h1 = __float2bfloat16(wv.y);
            __nv_bfloat16 h2 = __float2bfloat16(wv.z), h3 = __float2bfloat16(wv.w);
            float l0 = wv.x - __bfloat162float(h0), l1 = wv.y - __bfloat162float(h1);
            float l2 = wv.z - __bfloat162float(h2), l3 = wv.w - __bfloat162float(h3);
            ull hp = (ull)packh(h0, h1) | ((ull)packh(h2, h3) << 32);
            ull lp = (ull)packh(__float2bfloat16(l0), __float2bfloat16(l1))
                   | ((ull)packh(__float2bfloat16(l2), __float2bfloat16(l3)) << 32);
            u32 off = (u32)(n * 144 + k4 * 8);
            *(ull*)(smraw + OFF_W1H + off) = hp;
            *(ull*)(smraw + OFF_W1L + off) = lp;
        }
        __syncthreads();

        // -- MMAs over this chunk (4 k16 steps) --
#pragma unroll
        for (int k16 = 0; k16 < 4; k16++) {
            u32 bh[8], bl[8];
#pragma unroll
            for (int np = 0; np < 2; np++) {
                u32 boff = (bN + (u32)(np * 16)) * 144u + (u32)(k16 * 32) + bKof;
                ldsm4(bh + np * 4, sb + OFF_W1H + boff);
                ldsm4(bl + np * 4, sb + OFF_W1L + boff);
            }
#pragma unroll
            for (int mt = 0; mt < 2; mt++) {
                u32 aoff = (aRow + (u32)(mt * 16)) * 144u + (u32)(k16 * 32) + aKof;
                u32 ah[4], al[4];
                ldsm4(ah, sb + OFF_XH + aoff);
                ldsm4(al, sb + OFF_XL + aoff);
#pragma unroll
                for (int nt = 0; nt < 4; nt++) {
                    mma_bf16(acc[mt][nt], ah, bh + nt * 2);
                    mma_bf16(acc[mt][nt], al, bh + nt * 2);
                    mma_bf16(acc[mt][nt], ah, bl + nt * 2);
                }
            }
        }
        __syncthreads();
    }

    // -- spill fragments to mxs [row][col], stride 65 (aliases x staging) --
    {
        int g = lane >> 2, t = lane & 3;
#pragma unroll
        for (int mt = 0; mt < 2; mt++) {
            int r0 = mg * 32 + mt * 16 + g;
#pragma unroll
            for (int nt = 0; nt < 4; nt++) {
                int col = ng * 32 + nt * 8 + t * 2;
                mxs[r0 * 65 + col]           = acc[mt][nt][0];
                mxs[r0 * 65 + col + 1]       = acc[mt][nt][1];
                mxs[(r0 + 8) * 65 + col]     = acc[mt][nt][2];
                mxs[(r0 + 8) * 65 + col + 1] = acc[mt][nt][3];
            }
        }
    }
    x2s[xkh * 128 + xrow] = x2a;
    __syncthreads();

    // ---------------- Epilogue 1 (threads 0-127, one per row) ----------------
    if (tid < 128) {
        const int r0 = tid;
        float sx2 = x2s[r0] + x2s[128 + r0];
        float nx = fmaxf(sqrtf(sx2), MINN);
        float th = tanhf(nx);
        float al = th / nx;
        float xn1 = fmaxf(th, MINN);

        float p0 = 0.f, p1 = 0.f;
#pragma unroll
        for (int j = 0; j < HH; j++) {
            float v = al * mxs[r0 * 65 + j];
            p0 = fmaf(v, v, p0);
            p1 = fmaf(v, hb1s[j], p1);
        }
        float mxn = fmaxf(sqrtf(p0), MINN);
        float art = artanh_c(xn1);
        float t = tanhf(mxn / xn1 * art);
        float g = t / mxn;
        float rn = t;
        if (rn > MAXN) { g *= MAXN / rn; rn = MAXN; }
        float xy = g * p1;
        float x2 = rn * rn;
        float den = fmaxf(1.0f + 2.0f * xy + x2 * hb1sq, MINN);
        float A = (1.0f + 2.0f * xy + hb1sq) / den;
        float B = (1.0f - x2) / den;
        float nv2 = A * A * x2 + 2.0f * A * B * xy + B * B * hb1sq;
        float nv = sqrtf(nv2);
        float pf = (nv > MAXN) ? (MAXN / nv) : 1.0f;
        nv = fminf(nv, MAXN);
        float beta = artanh_c(nv) / fmaxf(nv, MINN);
        float C1a = beta * pf * A * g * al;
        float C2 = beta * pf * B;

        float xt_buf[HH];
        float p = 0.f;
#pragma unroll
        for (int j = 0; j < HH; j++) {
            float xt = C1a * mxs[r0 * 65 + j] + C2 * hb1s[j];
            xt = (xt > 0.0f) ? xt : 0.01f * xt;
            xt_buf[j] = xt;
            p = fmaf(xt, xt, p);
        }
        float nxt = fmaxf(sqrtf(p), MINN);
        float t2 = tanhf(nxt);
        float gam = t2 / nxt;
        if (t2 > MAXN) { gam *= MAXN / t2; t2 = MAXN; }
        un_s[r0] = fmaxf(t2, MINN);
#pragma unroll
        for (int j = 0; j < HH; j++)
            mxs[r0 * 65 + j] = gam * xt_buf[j];   // u in place
    }
    __syncthreads();

    // ---------------- GEMM2: mx2 = u @ W3^T  (f32x2 scalar) ----------------
    const int m = lane;
    ull acc2[4][8];
#pragma unroll
    for (int r = 0; r < 4; r++)
#pragma unroll
        for (int jj = 0; jj < 8; jj++) acc2[r][jj] = 0ull;

#pragma unroll 2
    for (int k = 0; k < HH; k++) {
        ull uvp[4];
#pragma unroll
        for (int r = 0; r < 4; r++) uvp[r] = dup2(mxs[(m + 32 * r) * 65 + k]);
        ull w[8];
#pragma unroll
        for (int jj = 0; jj < 8; jj++) w[jj] = *(ull*)(W3t + k * 128 + c * 16 + jj * 2);
#pragma unroll
        for (int jj = 0; jj < 8; jj++)
#pragma unroll
            for (int r = 0; r < 4; r++)
                acc2[r][jj] = ffma2(uvp[r], w[jj], acc2[r][jj]);
    }

    // R4: sum(mx2^2), sum(mx2*hb3)
#pragma unroll
    for (int r = 0; r < 4; r++) {
        ull p0 = 0ull, p1 = 0ull;
#pragma unroll
        for (int jj = 0; jj < 8; jj++) {
            ull hb = *(ull*)(hb3s + c * 16 + jj * 2);
            p0 = ffma2(acc2[r][jj], acc2[r][jj], p0);
            p1 = ffma2(acc2[r][jj], hb, p1);
        }
        red[c * 256 + (m + 32 * r)] = sum2(p0);
        red[c * 256 + 128 + (m + 32 * r)] = sum2(p1);
    }
    __syncthreads();
    {
        float s = 0.0f;
#pragma unroll
        for (int cc = 0; cc < 8; cc++) s += red[cc * 256 + tid];
        rdo[tid] = s;
    }
    __syncthreads();

    // Epilogue 2 + store
#pragma unroll
    for (int r = 0; r < 4; r++) {
        int rr = m + 32 * r;
        int grow = baseRow + rr;
        float un = un_s[rr];
        float mxn2 = rdo[rr];
        float dotb = rdo[128 + rr];
        float mxn = fmaxf(sqrtf(mxn2), MINN);
        float art = artanh_c(un);
        float t = tanhf(mxn / un * art);
        float g = t / mxn;
        float rn = t;
        if (rn > MAXN) { g *= MAXN / rn; rn = MAXN; }
        float xy = g * dotb;
        float x2 = rn * rn;
        float den = fmaxf(1.0f + 2.0f * xy + x2 * hb3sq, MINN);
        float A = (1.0f + 2.0f * xy + hb3sq) / den;
        float B = (1.0f - x2) / den;
        float nv2 = A * A * x2 + 2.0f * A * B * xy + B * B * hb3sq;
        float nv = sqrtf(nv2);
        float pf = (nv > MAXN) ? (MAXN / nv) : 1.0f;
        float cA = pf * A * g;
        float cB = pf * B;
        if (grow < N) {
            float* orow = out + (size_t)grow * DOUT + c * 16;
#pragma unroll
            for (int q = 0; q < 4; q++) {
                float l0, h0, l1, h1;
                unpack2(acc2[r][q * 2], l0, h0);
                unpack2(acc2[r][q * 2 + 1], l1, h1);
                float4 v;
                v.x = cA * l0 + cB * hb3s[c * 16 + q * 4 + 0];
                v.y = cA * h0 + cB * hb3s[c * 16 + q * 4 + 1];
                v.z = cA * l1 + cB * hb3s[c * 16 + q * 4 + 2];
                v.w = cA * h1 + cB * hb3s[c * 16 + q * 4 + 3];
                *(float4*)(orow + q * 4) = v;
            }
        }
    }
}

extern "C" void kernel_launch(void* const* d_in, const int* in_sizes, int n_in,
                              void* d_out, int out_size) {
    const float* x  = (const float*)d_in[0];
    const float* W1 = (const float*)d_in[1];
    const float* b1 = (const float*)d_in[2];
    const float* W3 = (const float*)d_in[3];
    const float* b3 = (const float*)d_in[4];
    float* out = (float*)d_out;
    int N = in_sizes[0] / DIN;

    cudaFuncSetAttribute(hnn_kernel, cudaFuncAttributeMaxDynamicSharedMemorySize, SMEM_BYTES);

    bias_kernel<<<1, 128>>>(b1, b3);
    hnn_kernel<<<(N + MT - 1) / MT, TPB, SMEM_BYTES>>>(x, W1, W3, out, N);
}

// round 5
// speedup vs baseline: 1.4951x; 1.1630x over previous
#include <cuda_runtime.h>
#include <cuda_bf16.h>
#include <math.h>
#include <stdint.h>

#define TPB   256
#define MT    128
#define DIN   512
#define HH    50
#define DOUT  128
#define MAXN  0.996f
#define MINN  1e-15f

typedef unsigned long long ull;
typedef uint32_t u32;

// ---- smem byte offsets ----
#define OFF_XH   0          // 128 rows * 144B (64 bf16 + pad)
#define OFF_XL   18432
#define OFF_W1H  36864      // 64 rows * 144B (rows 50..63 zero via padded global)
#define OFF_W1L  46080
#define OFF_MXS  0          // alias over XH/XL: 128 * 65 f32 = 33280B
#define OFF_W3T  55296      // 6400 f32
#define OFF_RED  80896      // 2048 f32
#define OFF_RDO  89088      // 256 f32
#define OFF_HB1  90112      // 64 f32
#define OFF_HB3  90368      // 128 f32
#define OFF_UNS  90880      // 128 f32
#define OFF_X2S  91392      // 256 f32
#define SMEM_BYTES 92416

__device__ float g_hb1[64];
__device__ float g_hb3[128];
__device__ float g_hb1sq, g_hb3sq;
// W1 pre-converted: [64][512] bf16, rows 50..63 zero
__device__ __align__(16) __nv_bfloat16 g_w1h[64 * 512];
__device__ __align__(16) __nv_bfloat16 g_w1l[64 * 512];

__device__ __forceinline__ float artanh_c(float z) {
    z = fminf(z, 1.0f - 1e-7f);
    return 0.5f * logf((1.0f + z) / (1.0f - z));
}

// ---- f32x2 helpers (GEMM2) ----
__device__ __forceinline__ ull ffma2(ull a, ull b, ull c) {
    ull d; asm("fma.rn.f32x2 %0, %1, %2, %3;" : "=l"(d) : "l"(a), "l"(b), "l"(c)); return d;
}
__device__ __forceinline__ ull dup2(float x) {
    ull d; asm("mov.b64 %0, {%1, %1};" : "=l"(d) : "f"(x)); return d;
}
__device__ __forceinline__ float sum2(ull p) {
    float lo, hi; asm("mov.b64 {%0, %1}, %2;" : "=f"(lo), "=f"(hi) : "l"(p)); return lo + hi;
}
__device__ __forceinline__ void unpack2(ull p, float& lo, float& hi) {
    asm("mov.b64 {%0, %1}, %2;" : "=f"(lo), "=f"(hi) : "l"(p));
}

// ---- HMMA / async helpers ----
__device__ __forceinline__ void mma_bf16(float* d, const u32* a, const u32* b) {
    asm("mma.sync.aligned.m16n8k16.row.col.f32.bf16.bf16.f32 "
        "{%0,%1,%2,%3}, {%4,%5,%6,%7}, {%8,%9}, {%0,%1,%2,%3};"
        : "+f"(d[0]), "+f"(d[1]), "+f"(d[2]), "+f"(d[3])
        : "r"(a[0]), "r"(a[1]), "r"(a[2]), "r"(a[3]), "r"(b[0]), "r"(b[1]));
}
__device__ __forceinline__ void ldsm4(u32* r, u32 addr) {
    asm volatile("ldmatrix.sync.aligned.m8n8.x4.shared.b16 {%0,%1,%2,%3}, [%4];"
        : "=r"(r[0]), "=r"(r[1]), "=r"(r[2]), "=r"(r[3]) : "r"(addr));
}
__device__ __forceinline__ u32 packh(__nv_bfloat16 a, __nv_bfloat16 b) {
    __nv_bfloat162 t = __halves2bfloat162(a, b);
    return *reinterpret_cast<u32*>(&t);
}
__device__ __forceinline__ void cp_async16(u32 sdst, const void* gsrc) {
    asm volatile("cp.async.ca.shared.global [%0], [%1], 16;" :: "r"(sdst), "l"(gsrc));
}
__device__ __forceinline__ void cp_wait_all() {
    asm volatile("cp.async.commit_group;\n\tcp.async.wait_group 0;" ::: "memory");
}

// setup 1: hyp_b = proj(expmap0(b)); also ||hyp_b||^2
__global__ void bias_kernel(const float* __restrict__ b1, const float* __restrict__ b3) {
    __shared__ float s[128];
    int t = threadIdx.x;

    float v1 = (t < HH) ? b1[t] : 0.0f;
    s[t] = v1 * v1;
    __syncthreads();
    for (int o = 64; o > 0; o >>= 1) { if (t < o) s[t] += s[t + o]; __syncthreads(); }
    float nb2 = s[0];
    __syncthreads();
    {
        float nb = fmaxf(sqrtf(nb2), MINN);
        float th = tanhf(nb);
        float sc = th / nb;
        if (th > MAXN) { sc *= MAXN / th; th = MAXN; }
        if (t < HH) g_hb1[t] = sc * v1;
        if (t == 0) g_hb1sq = th * th;
    }

    float v3 = b3[t];
    s[t] = v3 * v3;
    __syncthreads();
    for (int o = 64; o > 0; o >>= 1) { if (t < o) s[t] += s[t + o]; __syncthreads(); }
    nb2 = s[0];
    __syncthreads();
    {
        float nb = fmaxf(sqrtf(nb2), MINN);
        float th = tanhf(nb);
        float sc = th / nb;
        if (th > MAXN) { sc *= MAXN / th; th = MAXN; }
        g_hb3[t] = sc * v3;
        if (t == 0) g_hb3sq = th * th;
    }
}

// setup 2: W1 -> bf16 hi/lo, zero-padded to 64 rows
__global__ void w1prep_kernel(const float* __restrict__ W1) {
    int idx = blockIdx.x * blockDim.x + threadIdx.x;   // 0..32767
    int row = idx >> 9;
    float v = (row < HH) ? W1[(size_t)row * DIN + (idx & 511)] : 0.0f;
    __nv_bfloat16 h = __float2bfloat16(v);
    g_w1h[idx] = h;
    g_w1l[idx] = __float2bfloat16(v - __bfloat162float(h));
}

extern __shared__ __align__(1024) char smraw[];

__global__ __launch_bounds__(TPB, 2)
void hnn_kernel(const float* __restrict__ X, const float* __restrict__ W3,
                float* __restrict__ out, int N)
{
    const u32 sb = (u32)__cvta_generic_to_shared(smraw);
    float* mxs  = (float*)(smraw + OFF_MXS);   // [row][j], stride 65
    float* W3t  = (float*)(smraw + OFF_W3T);   // [k][j], stride 128
    float* red  = (float*)(smraw + OFF_RED);
    float* rdo  = (float*)(smraw + OFF_RDO);
    float* hb1s = (float*)(smraw + OFF_HB1);
    float* hb3s = (float*)(smraw + OFF_HB3);
    float* un_s = (float*)(smraw + OFF_UNS);
    float* x2s  = (float*)(smraw + OFF_X2S);

    const int tid = threadIdx.x;
    const int lane = tid & 31;
    const int c = tid >> 5;           // warp id
    const int mg = c & 3;             // row group (32 rows)
    const int ng = c >> 2;            // col group (32 cols)
    const int baseRow = blockIdx.x * MT;

    for (int i = tid; i < DOUT * HH; i += TPB) {
        int j = i / HH, k = i - j * HH;
        W3t[k * 128 + j] = W3[i];
    }
    for (int i = tid; i < 64; i += TPB) hb1s[i] = (i < HH) ? g_hb1[i] : 0.0f;
    if (tid < DOUT) hb3s[tid] = g_hb3[tid];
    const float hb1sq = g_hb1sq;
    const float hb3sq = g_hb3sq;

    // ---------------- GEMM1: mx_raw = x @ W1^T  (HMMA bf16, 3-way split) ----------------
    const int xrow = tid & 127;
    const int xkh  = tid >> 7;        // which 32-k half this thread loads
    const int gr = baseRow + xrow;
    const bool valid = gr < N;
    const float* xptr = X + (size_t)gr * DIN + xkh * 32;
    float x2a = 0.0f;

    float acc[2][4][4];
#pragma unroll
    for (int mt = 0; mt < 2; mt++)
#pragma unroll
        for (int nt = 0; nt < 4; nt++)
#pragma unroll
            for (int e = 0; e < 4; e++) acc[mt][nt][e] = 0.0f;

    // ldmatrix lane address components
    const u32 aRow = (u32)(mg * 32 + (lane & 15));
    const u32 aKof = (u32)((lane >> 4) * 16);
    const u32 bN   = (u32)(ng * 32 + ((lane >> 4) * 8) + (lane & 7));
    const u32 bKof = (u32)(((lane >> 3) & 1) * 16);

    // W1 cp.async addressing (4 units of 16B per thread per chunk)
    // unit u = tid + 256*p, p<4; half = u>>9; n = (u>>3)&63; j = u&7
    u32 w1_sdst[4];
    const __nv_bfloat16* w1_gsrc[4];
#pragma unroll
    for (int p = 0; p < 4; p++) {
        int u = tid + 256 * p;
        int half = u >> 9, n = (u >> 3) & 63, j = u & 7;
        w1_sdst[p] = sb + OFF_W1H + (u32)(half * 9216 + n * 144 + j * 16);
        w1_gsrc[p] = (half ? g_w1l : g_w1h) + n * 512 + j * 8;
    }

    // prologue: prefetch x chunk 0
    float4 xr[8];
#pragma unroll
    for (int q = 0; q < 8; q++)
        xr[q] = valid ? *(const float4*)(xptr + q * 4) : make_float4(0.f, 0.f, 0.f, 0.f);
    __syncthreads();   // W3t/hb ready; (first iteration: X smem trivially free)

    for (int kc = 0; kc < 8; kc++) {
        // -- stage x chunk kc from registers (convert to hi/lo bf16) --
#pragma unroll
        for (int q = 0; q < 8; q++) {
            float4 v = xr[q];
            __nv_bfloat16 h0 = __float2bfloat16(v.x), h1 = __float2bfloat16(v.y);
            __nv_bfloat16 h2 = __float2bfloat16(v.z), h3 = __float2bfloat16(v.w);
            float l0 = v.x - __bfloat162float(h0), l1 = v.y - __bfloat162float(h1);
            float l2 = v.z - __bfloat162float(h2), l3 = v.w - __bfloat162float(h3);
            ull hp = (ull)packh(h0, h1) | ((ull)packh(h2, h3) << 32);
            ull lp = (ull)packh(__float2bfloat16(l0), __float2bfloat16(l1))
                   | ((ull)packh(__float2bfloat16(l2), __float2bfloat16(l3)) << 32);
            u32 off = (u32)(xrow * 144 + xkh * 64 + q * 8);
            *(ull*)(smraw + OFF_XH + off) = hp;
            *(ull*)(smraw + OFF_XL + off) = lp;
            x2a = fmaf(v.x, v.x, fmaf(v.y, v.y, fmaf(v.z, v.z, fmaf(v.w, v.w, x2a))));
        }
        // -- W1 chunk kc via cp.async (pre-converted bf16, pad rows zero) --
#pragma unroll
        for (int p = 0; p < 4; p++)
            cp_async16(w1_sdst[p], w1_gsrc[p] + kc * 64);

        // -- prefetch x chunk kc+1 into registers (in flight during MMA) --
        if (kc < 7) {
#pragma unroll
            for (int q = 0; q < 8; q++)
                xr[q] = valid ? *(const float4*)(xptr + (kc + 1) * 64 + q * 4)
                              : make_float4(0.f, 0.f, 0.f, 0.f);
        }

        cp_wait_all();
        __syncthreads();

        // -- MMAs over this chunk (4 k16 steps) --
#pragma unroll
        for (int k16 = 0; k16 < 4; k16++) {
            u32 bh[8], bl[8];
#pragma unroll
            for (int np = 0; np < 2; np++) {
                u32 boff = (bN + (u32)(np * 16)) * 144u + (u32)(k16 * 32) + bKof;
                ldsm4(bh + np * 4, sb + OFF_W1H + boff);
                ldsm4(bl + np * 4, sb + OFF_W1L + boff);
            }
#pragma unroll
            for (int mt = 0; mt < 2; mt++) {
                u32 aoff = (aRow + (u32)(mt * 16)) * 144u + (u32)(k16 * 32) + aKof;
                u32 ah[4], al[4];
                ldsm4(ah, sb + OFF_XH + aoff);
                ldsm4(al, sb + OFF_XL + aoff);
#pragma unroll
                for (int nt = 0; nt < 4; nt++) {
                    mma_bf16(acc[mt][nt], ah, bh + nt * 2);
                    mma_bf16(acc[mt][nt], al, bh + nt * 2);
                    mma_bf16(acc[mt][nt], ah, bl + nt * 2);
                }
            }
        }
        __syncthreads();
    }

    // -- spill fragments to mxs [row][col], stride 65 (aliases x staging) --
    {
        int g = lane >> 2, t = lane & 3;
#pragma unroll
        for (int mt = 0; mt < 2; mt++) {
            int r0 = mg * 32 + mt * 16 + g;
#pragma unroll
            for (int nt = 0; nt < 4; nt++) {
                int col = ng * 32 + nt * 8 + t * 2;
                mxs[r0 * 65 + col]           = acc[mt][nt][0];
                mxs[r0 * 65 + col + 1]       = acc[mt][nt][1];
                mxs[(r0 + 8) * 65 + col]     = acc[mt][nt][2];
                mxs[(r0 + 8) * 65 + col + 1] = acc[mt][nt][3];
            }
        }
    }
    x2s[xkh * 128 + xrow] = x2a;
    __syncthreads();

    // ---------------- Epilogue 1 (threads 0-127, one per row) ----------------
    if (tid < 128) {
        const int r0 = tid;
        float sx2 = x2s[r0] + x2s[128 + r0];
        float nx = fmaxf(sqrtf(sx2), MINN);
        float th = tanhf(nx);
        float al = th / nx;
        float xn1 = fmaxf(th, MINN);

        float p0 = 0.f, p1 = 0.f;
#pragma unroll
        for (int j = 0; j < HH; j++) {
            float v = al * mxs[r0 * 65 + j];
            p0 = fmaf(v, v, p0);
            p1 = fmaf(v, hb1s[j], p1);
        }
        float mxn = fmaxf(sqrtf(p0), MINN);
        float art = artanh_c(xn1);
        float t = tanhf(mxn / xn1 * art);
        float g = t / mxn;
        float rn = t;
        if (rn > MAXN) { g *= MAXN / rn; rn = MAXN; }
        float xy = g * p1;
        float x2 = rn * rn;
        float den = fmaxf(1.0f + 2.0f * xy + x2 * hb1sq, MINN);
        float A = (1.0f + 2.0f * xy + hb1sq) / den;
        float B = (1.0f - x2) / den;
        float nv2 = A * A * x2 + 2.0f * A * B * xy + B * B * hb1sq;
        float nv = sqrtf(nv2);
        float pf = (nv > MAXN) ? (MAXN / nv) : 1.0f;
        nv = fminf(nv, MAXN);
        float beta = artanh_c(nv) / fmaxf(nv, MINN);
        float C1a = beta * pf * A * g * al;
        float C2 = beta * pf * B;

        float xt_buf[HH];
        float p = 0.f;
#pragma unroll
        for (int j = 0; j < HH; j++) {
            float xt = C1a * mxs[r0 * 65 + j] + C2 * hb1s[j];
            xt = (xt > 0.0f) ? xt : 0.01f * xt;
            xt_buf[j] = xt;
            p = fmaf(xt, xt, p);
        }
        float nxt = fmaxf(sqrtf(p), MINN);
        float t2 = tanhf(nxt);
        float gam = t2 / nxt;
        if (t2 > MAXN) { gam *= MAXN / t2; t2 = MAXN; }
        un_s[r0] = fmaxf(t2, MINN);
#pragma unroll
        for (int j = 0; j < HH; j++)
            mxs[r0 * 65 + j] = gam * xt_buf[j];   // u in place
    }
    __syncthreads();

    // ---------------- GEMM2: mx2 = u @ W3^T  (f32x2 scalar) ----------------
    const int m = lane;
    ull acc2[4][8];
#pragma unroll
    for (int r = 0; r < 4; r++)
#pragma unroll
        for (int jj = 0; jj < 8; jj++) acc2[r][jj] = 0ull;

#pragma unroll 2
    for (int k = 0; k < HH; k++) {
        ull uvp[4];
#pragma unroll
        for (int r = 0; r < 4; r++) uvp[r] = dup2(mxs[(m + 32 * r) * 65 + k]);
        ull w[8];
#pragma unroll
        for (int jj = 0; jj < 8; jj++) w[jj] = *(ull*)(W3t + k * 128 + c * 16 + jj * 2);
#pragma unroll
        for (int jj = 0; jj < 8; jj++)
#pragma unroll
            for (int r = 0; r < 4; r++)
                acc2[r][jj] = ffma2(uvp[r], w[jj], acc2[r][jj]);
    }

    // R4: sum(mx2^2), sum(mx2*hb3)
#pragma unroll
    for (int r = 0; r < 4; r++) {
        ull p0 = 0ull, p1 = 0ull;
#pragma unroll
        for (int jj = 0; jj < 8; jj++) {
            ull hb = *(ull*)(hb3s + c * 16 + jj * 2);
            p0 = ffma2(acc2[r][jj], acc2[r][jj], p0);
            p1 = ffma2(acc2[r][jj], hb, p1);
        }
        red[c * 256 + (m + 32 * r)] = sum2(p0);
        red[c * 256 + 128 + (m + 32 * r)] = sum2(p1);
    }
    __syncthreads();
    {
        float s = 0.0f;
#pragma unroll
        for (int cc = 0; cc < 8; cc++) s += red[cc * 256 + tid];
        rdo[tid] = s;
    }
    __syncthreads();

    // Epilogue 2 + store
#pragma unroll
    for (int r = 0; r < 4; r++) {
        int rr = m + 32 * r;
        int grow = baseRow + rr;
        float un = un_s[rr];
        float mxn2 = rdo[rr];
        float dotb = rdo[128 + rr];
        float mxn = fmaxf(sqrtf(mxn2), MINN);
        float art = artanh_c(un);
        float t = tanhf(mxn / un * art);
        float g = t / mxn;
        float rn = t;
        if (rn > MAXN) { g *= MAXN / rn; rn = MAXN; }
        float xy = g * dotb;
        float x2 = rn * rn;
        float den = fmaxf(1.0f + 2.0f * xy + x2 * hb3sq, MINN);
        float A = (1.0f + 2.0f * xy + hb3sq) / den;
        float B = (1.0f - x2) / den;
        float nv2 = A * A * x2 + 2.0f * A * B * xy + B * B * hb3sq;
        float nv = sqrtf(nv2);
        float pf = (nv > MAXN) ? (MAXN / nv) : 1.0f;
        float cA = pf * A * g;
        float cB = pf * B;
        if (grow < N) {
            float* orow = out + (size_t)grow * DOUT + c * 16;
#pragma unroll
            for (int q = 0; q < 4; q++) {
                float l0, h0, l1, h1;
                unpack2(acc2[r][q * 2], l0, h0);
                unpack2(acc2[r][q * 2 + 1], l1, h1);
                float4 v;
                v.x = cA * l0 + cB * hb3s[c * 16 + q * 4 + 0];
                v.y = cA * h0 + cB * hb3s[c * 16 + q * 4 + 1];
                v.z = cA * l1 + cB * hb3s[c * 16 + q * 4 + 2];
                v.w = cA * h1 + cB * hb3s[c * 16 + q * 4 + 3];
                *(float4*)(orow + q * 4) = v;
            }
        }
    }
}

extern "C" void kernel_launch(void* const* d_in, const int* in_sizes, int n_in,
                              void* d_out, int out_size) {
    const float* x  = (const float*)d_in[0];
    const float* W1 = (const float*)d_in[1];
    const float* b1 = (const float*)d_in[2];
    const float* W3 = (const float*)d_in[3];
    const float* b3 = (const float*)d_in[4];
    float* out = (float*)d_out;
    int N = in_sizes[0] / DIN;

    cudaFuncSetAttribute(hnn_kernel, cudaFuncAttributeMaxDynamicSharedMemorySize, SMEM_BYTES);

    bias_kernel<<<1, 128>>>(b1, b3);
    w1prep_kernel<<<128, 256>>>(W1);
    hnn_kernel<<<(N + MT - 1) / MT, TPB, SMEM_BYTES>>>(x, W3, out, N);
}

// round 6
// speedup vs baseline: 1.7263x; 1.1547x over previous
#include <cuda_runtime.h>
#include <cuda_bf16.h>
#include <math.h>
#include <stdint.h>

#define TPB   256
#define MT    128
#define DIN   512
#define HH    50
#define DOUT  128
#define MAXN  0.996f
#define MINN  1e-15f

typedef unsigned long long ull;
typedef uint32_t u32;

// ---- smem byte offsets ----
#define OFF_W3H  0          // 128 x 144B  (bf16 [n][k64] + pad), resident
#define OFF_W3L  18432
#define OFF_XH   36864      // 128 x 144B  per-tile x staging (hi)
#define OFF_XL   55296
#define OFF_W1H  73728      // 64 x 144B
#define OFF_W1L  82944
#define OFF_MXS  36864      // alias XH/XL: 128*65 f32 = 33280B
#define OFF_UH   73728      // alias W1H/L: 128 x 144B (u hi)
#define OFF_UL   92160      // 128 x 144B (u lo)
#define OFF_HB1  110592     // 64 f32
#define OFF_HB3  110848     // 128 f32
#define OFF_X2S  111360     // 256 f32
#define OFF_UNS  112384     // 128 f32
#define SMEM_BYTES 112896

__device__ float g_hb1[64];
__device__ float g_hb3[128];
__device__ float g_hb1sq, g_hb3sq;
__device__ __align__(16) __nv_bfloat16 g_w1h[64 * 512];   // rows 50..63 zero
__device__ __align__(16) __nv_bfloat16 g_w1l[64 * 512];
__device__ __align__(16) __nv_bfloat16 g_w3h[128 * 64];   // k 50..63 zero
__device__ __align__(16) __nv_bfloat16 g_w3l[128 * 64];

__device__ __forceinline__ float artanh_c(float z) {
    z = fminf(z, 1.0f - 1e-7f);
    return 0.5f * logf((1.0f + z) / (1.0f - z));
}

// ---- HMMA / async helpers ----
__device__ __forceinline__ void mma_bf16(float* d, const u32* a, const u32* b) {
    asm("mma.sync.aligned.m16n8k16.row.col.f32.bf16.bf16.f32 "
        "{%0,%1,%2,%3}, {%4,%5,%6,%7}, {%8,%9}, {%0,%1,%2,%3};"
        : "+f"(d[0]), "+f"(d[1]), "+f"(d[2]), "+f"(d[3])
        : "r"(a[0]), "r"(a[1]), "r"(a[2]), "r"(a[3]), "r"(b[0]), "r"(b[1]));
}
__device__ __forceinline__ void ldsm4(u32* r, u32 addr) {
    asm volatile("ldmatrix.sync.aligned.m8n8.x4.shared.b16 {%0,%1,%2,%3}, [%4];"
        : "=r"(r[0]), "=r"(r[1]), "=r"(r[2]), "=r"(r[3]) : "r"(addr));
}
__device__ __forceinline__ u32 packh(__nv_bfloat16 a, __nv_bfloat16 b) {
    __nv_bfloat162 t = __halves2bfloat162(a, b);
    return *reinterpret_cast<u32*>(&t);
}
__device__ __forceinline__ void cp_async16(u32 sdst, const void* gsrc) {
    asm volatile("cp.async.ca.shared.global [%0], [%1], 16;" :: "r"(sdst), "l"(gsrc));
}
__device__ __forceinline__ void cp_wait_all() {
    asm volatile("cp.async.commit_group;\n\tcp.async.wait_group 0;" ::: "memory");
}

// setup 1: hyp_b = proj(expmap0(b)); also ||hyp_b||^2
__global__ void bias_kernel(const float* __restrict__ b1, const float* __restrict__ b3) {
    __shared__ float s[128];
    int t = threadIdx.x;

    float v1 = (t < HH) ? b1[t] : 0.0f;
    s[t] = v1 * v1;
    __syncthreads();
    for (int o = 64; o > 0; o >>= 1) { if (t < o) s[t] += s[t + o]; __syncthreads(); }
    float nb2 = s[0];
    __syncthreads();
    {
        float nb = fmaxf(sqrtf(nb2), MINN);
        float th = tanhf(nb);
        float sc = th / nb;
        if (th > MAXN) { sc *= MAXN / th; th = MAXN; }
        if (t < HH) g_hb1[t] = sc * v1;
        if (t == 0) g_hb1sq = th * th;
    }

    float v3 = b3[t];
    s[t] = v3 * v3;
    __syncthreads();
    for (int o = 64; o > 0; o >>= 1) { if (t < o) s[t] += s[t + o]; __syncthreads(); }
    nb2 = s[0];
    __syncthreads();
    {
        float nb = fmaxf(sqrtf(nb2), MINN);
        float th = tanhf(nb);
        float sc = th / nb;
        if (th > MAXN) { sc *= MAXN / th; th = MAXN; }
        g_hb3[t] = sc * v3;
        if (t == 0) g_hb3sq = th * th;
    }
}

// setup 2: W1 and W3 -> bf16 hi/lo, zero-padded
__global__ void prep_kernel(const float* __restrict__ W1, const float* __restrict__ W3) {
    int idx = blockIdx.x * blockDim.x + threadIdx.x;
    if (idx < 64 * 512) {
        int row = idx >> 9;
        float v = (row < HH) ? W1[(size_t)row * DIN + (idx & 511)] : 0.0f;
        __nv_bfloat16 h = __float2bfloat16(v);
        g_w1h[idx] = h;
        g_w1l[idx] = __float2bfloat16(v - __bfloat162float(h));
    } else if (idx < 64 * 512 + 128 * 64) {
        int i = idx - 64 * 512;
        int n = i >> 6, k = i & 63;
        float v = (k < HH) ? W3[(size_t)n * HH + k] : 0.0f;
        __nv_bfloat16 h = __float2bfloat16(v);
        g_w3h[i] = h;
        g_w3l[i] = __float2bfloat16(v - __bfloat162float(h));
    }
}

extern __shared__ __align__(1024) char smraw[];

__global__ __launch_bounds__(TPB, 2)
void hnn_kernel(const float* __restrict__ X, float* __restrict__ out, int N, int nTiles)
{
    const u32 sb = (u32)__cvta_generic_to_shared(smraw);
    float* mxs  = (float*)(smraw + OFF_MXS);   // [row][j], stride 65
    float* hb1s = (float*)(smraw + OFF_HB1);
    float* hb3s = (float*)(smraw + OFF_HB3);
    float* x2s  = (float*)(smraw + OFF_X2S);
    float* un_s = (float*)(smraw + OFF_UNS);

    const int tid = threadIdx.x;
    const int lane = tid & 31;
    const int c = tid >> 5;           // warp id
    const int mg = c & 3;             // GEMM1 row group
    const int ng = c >> 2;            // GEMM1 col group

    // resident: W3 hi/lo into smem via cp.async; biases
    for (int i = tid; i < 1024; i += TPB) {
        int n = i >> 3, j = i & 7;
        cp_async16(sb + OFF_W3H + (u32)(n * 144 + j * 16), g_w3h + n * 64 + j * 8);
        cp_async16(sb + OFF_W3L + (u32)(n * 144 + j * 16), g_w3l + n * 64 + j * 8);
    }
    for (int i = tid; i < 64; i += TPB) hb1s[i] = (i < HH) ? g_hb1[i] : 0.0f;
    if (tid < DOUT) hb3s[tid] = g_hb3[tid];
    const float hb1sq = g_hb1sq;
    const float hb3sq = g_hb3sq;

    // per-thread constants
    const int xrow = tid & 127;
    const int xkh  = tid >> 7;
    // GEMM1 ldmatrix lane components
    const u32 aRow = (u32)(mg * 32 + (lane & 15));
    const u32 aKof = (u32)((lane >> 4) * 16);
    const u32 bN   = (u32)(ng * 32 + ((lane >> 4) * 8) + (lane & 7));
    const u32 bKof = (u32)(((lane >> 3) & 1) * 16);
    // GEMM2 lane components
    const u32 a2H = sb + OFF_UH + (u32)((c * 16 + (lane & 15)) * 144 + (lane >> 4) * 16);
    const u32 a2L = a2H + (OFF_UL - OFF_UH);
    const u32 b2H = sb + OFF_W3H + (u32)((((lane >> 4) * 8) + (lane & 7)) * 144 + ((lane >> 3) & 1) * 16);
    const u32 b2L = b2H + (OFF_W3L - OFF_W3H);
    const int g2 = lane >> 2, t2 = lane & 3;

    // W1 cp.async addressing
    u32 w1_sdst[4];
    const __nv_bfloat16* w1_gsrc[4];
#pragma unroll
    for (int p = 0; p < 4; p++) {
        int u = tid + 256 * p;
        int half = u >> 9, n = (u >> 3) & 63, j = u & 7;
        w1_sdst[p] = sb + OFF_W1H + (u32)(half * 9216 + n * 144 + j * 16);
        w1_gsrc[p] = (half ? g_w1l : g_w1h) + n * 512 + j * 8;
    }

    for (int tile = blockIdx.x; tile < nTiles; tile += gridDim.x) {
        const int baseRow = tile * MT;
        const int gr = baseRow + xrow;
        const bool valid = gr < N;
        const float* xptr = X + (size_t)gr * DIN + xkh * 32;
        float x2a = 0.0f;

        // prefetch x chunk 0 (global reads only — safe before sync)
        float4 xr[8];
#pragma unroll
        for (int q = 0; q < 8; q++)
            xr[q] = valid ? *(const float4*)(xptr + q * 4) : make_float4(0.f, 0.f, 0.f, 0.f);

        __syncthreads();   // prior tile's GEMM2 reads done before we overwrite staging

        float acc[2][4][4];
#pragma unroll
        for (int mt = 0; mt < 2; mt++)
#pragma unroll
            for (int nt = 0; nt < 4; nt++)
#pragma unroll
                for (int e = 0; e < 4; e++) acc[mt][nt][e] = 0.0f;

        // -------- GEMM1: x @ W1^T (HMMA bf16, 3-way split) --------
        for (int kc = 0; kc < 8; kc++) {
            ull hp[8], lp[8];
#pragma unroll
            for (int q = 0; q < 8; q++) {
                float4 v = xr[q];
                __nv_bfloat16 h0 = __float2bfloat16(v.x), h1 = __float2bfloat16(v.y);
                __nv_bfloat16 h2 = __float2bfloat16(v.z), h3 = __float2bfloat16(v.w);
                float l0 = v.x - __bfloat162float(h0), l1 = v.y - __bfloat162float(h1);
                float l2 = v.z - __bfloat162float(h2), l3 = v.w - __bfloat162float(h3);
                hp[q] = (ull)packh(h0, h1) | ((ull)packh(h2, h3) << 32);
                lp[q] = (ull)packh(__float2bfloat16(l0), __float2bfloat16(l1))
                      | ((ull)packh(__float2bfloat16(l2), __float2bfloat16(l3)) << 32);
                x2a = fmaf(v.x, v.x, fmaf(v.y, v.y, fmaf(v.z, v.z, fmaf(v.w, v.w, x2a))));
            }
            {
                u32 off = (u32)(xrow * 144 + xkh * 64);
#pragma unroll
                for (int q = 0; q < 8; q += 2) {
                    ulonglong2 hv; hv.x = hp[q]; hv.y = hp[q + 1];
                    ulonglong2 lv; lv.x = lp[q]; lv.y = lp[q + 1];
                    *(ulonglong2*)(smraw + OFF_XH + off + q * 8) = hv;
                    *(ulonglong2*)(smraw + OFF_XL + off + q * 8) = lv;
                }
            }
#pragma unroll
            for (int p = 0; p < 4; p++)
                cp_async16(w1_sdst[p], w1_gsrc[p] + kc * 64);

            if (kc < 7) {
#pragma unroll
                for (int q = 0; q < 8; q++)
                    xr[q] = valid ? *(const float4*)(xptr + (kc + 1) * 64 + q * 4)
                                  : make_float4(0.f, 0.f, 0.f, 0.f);
            }
            cp_wait_all();
            __syncthreads();

#pragma unroll
            for (int k16 = 0; k16 < 4; k16++) {
                u32 bh[8], bl[8];
#pragma unroll
                for (int np = 0; np < 2; np++) {
                    u32 boff = (bN + (u32)(np * 16)) * 144u + (u32)(k16 * 32) + bKof;
                    ldsm4(bh + np * 4, sb + OFF_W1H + boff);
                    ldsm4(bl + np * 4, sb + OFF_W1L + boff);
                }
#pragma unroll
                for (int mt = 0; mt < 2; mt++) {
                    u32 aoff = (aRow + (u32)(mt * 16)) * 144u + (u32)(k16 * 32) + aKof;
                    u32 ah[4], al[4];
                    ldsm4(ah, sb + OFF_XH + aoff);
                    ldsm4(al, sb + OFF_XL + aoff);
#pragma unroll
                    for (int nt = 0; nt < 4; nt++) {
                        mma_bf16(acc[mt][nt], ah, bh + nt * 2);
                        mma_bf16(acc[mt][nt], al, bh + nt * 2);
                        mma_bf16(acc[mt][nt], ah, bl + nt * 2);
                    }
                }
            }
            __syncthreads();
        }

        // spill fragments to mxs [row][col] stride 65 (aliases x staging)
        {
            int g = lane >> 2, t = lane & 3;
#pragma unroll
            for (int mt = 0; mt < 2; mt++) {
                int r0 = mg * 32 + mt * 16 + g;
#pragma unroll
                for (int nt = 0; nt < 4; nt++) {
                    int col = ng * 32 + nt * 8 + t * 2;
                    mxs[r0 * 65 + col]           = acc[mt][nt][0];
                    mxs[r0 * 65 + col + 1]       = acc[mt][nt][1];
                    mxs[(r0 + 8) * 65 + col]     = acc[mt][nt][2];
                    mxs[(r0 + 8) * 65 + col + 1] = acc[mt][nt][3];
                }
            }
        }
        x2s[xkh * 128 + xrow] = x2a;
        __syncthreads();

        // -------- Epilogue 1 (threads 0..127, one per row) --------
        if (tid < 128) {
            const int r0 = tid;
            float sx2 = x2s[r0] + x2s[128 + r0];
            float nx = fmaxf(sqrtf(sx2), MINN);
            float th = tanhf(nx);
            float al = th / nx;
            float xn1 = fmaxf(th, MINN);

            float p0 = 0.f, p1 = 0.f;
#pragma unroll
            for (int j = 0; j < HH; j++) {
                float v = al * mxs[r0 * 65 + j];
                p0 = fmaf(v, v, p0);
                p1 = fmaf(v, hb1s[j], p1);
            }
            float mxn = fmaxf(sqrtf(p0), MINN);
            float art = artanh_c(xn1);
            float t = tanhf(mxn / xn1 * art);
            float g = t / mxn;
            float rn = t;
            if (rn > MAXN) { g *= MAXN / rn; rn = MAXN; }
            float xy = g * p1;
            float x2 = rn * rn;
            float den = fmaxf(1.0f + 2.0f * xy + x2 * hb1sq, MINN);
            float A = (1.0f + 2.0f * xy + hb1sq) / den;
            float B = (1.0f - x2) / den;
            float nv2 = A * A * x2 + 2.0f * A * B * xy + B * B * hb1sq;
            float nv = sqrtf(nv2);
            float pf = (nv > MAXN) ? (MAXN / nv) : 1.0f;
            nv = fminf(nv, MAXN);
            float beta = artanh_c(nv) / fmaxf(nv, MINN);
            float C1a = beta * pf * A * g * al;
            float C2 = beta * pf * B;

            float xt_buf[HH];
            float p = 0.f;
#pragma unroll
            for (int j = 0; j < HH; j++) {
                float xt = C1a * mxs[r0 * 65 + j] + C2 * hb1s[j];
                xt = (xt > 0.0f) ? xt : 0.01f * xt;
                xt_buf[j] = xt;
                p = fmaf(xt, xt, p);
            }
            float nxt = fmaxf(sqrtf(p), MINN);
            float t3 = tanhf(nxt);
            float gam = t3 / nxt;
            if (t3 > MAXN) { gam *= MAXN / t3; t3 = MAXN; }
            un_s[r0] = fmaxf(t3, MINN);

            // write u as bf16 hi/lo into ldmatrix layout (k padded to 64 with zeros)
#pragma unroll
            for (int jj = 0; jj < 32; jj++) {
                int j0 = jj * 2;
                float v0 = (j0 < HH) ? gam * xt_buf[j0] : 0.0f;
                float v1 = (j0 + 1 < HH) ? gam * xt_buf[j0 + 1] : 0.0f;
                __nv_bfloat16 h0 = __float2bfloat16(v0), h1 = __float2bfloat16(v1);
                float l0 = v0 - __bfloat162float(h0), l1 = v1 - __bfloat162float(h1);
                *(u32*)(smraw + OFF_UH + r0 * 144 + jj * 4) = packh(h0, h1);
                *(u32*)(smraw + OFF_UL + r0 * 144 + jj * 4) =
                    packh(__float2bfloat16(l0), __float2bfloat16(l1));
            }
        }
        __syncthreads();

        // -------- GEMM2: u @ W3^T  (HMMA bf16, 3-way split; 16 rows/warp) --------
        float acc2[16][4];
#pragma unroll
        for (int nt = 0; nt < 16; nt++)
#pragma unroll
            for (int e = 0; e < 4; e++) acc2[nt][e] = 0.0f;

#pragma unroll
        for (int k16 = 0; k16 < 4; k16++) {
            u32 ah[4], al[4];
            ldsm4(ah, a2H + (u32)(k16 * 32));
            ldsm4(al, a2L + (u32)(k16 * 32));
#pragma unroll
            for (int np = 0; np < 8; np++) {
                u32 bh[4], bl[4];
                u32 boff = (u32)(np * 2304 + k16 * 32);
                ldsm4(bh, b2H + boff);
                ldsm4(bl, b2L + boff);
#pragma unroll
                for (int npi = 0; npi < 2; npi++) {
                    mma_bf16(acc2[np * 2 + npi], ah, bh + npi * 2);
                    mma_bf16(acc2[np * 2 + npi], al, bh + npi * 2);
                    mma_bf16(acc2[np * 2 + npi], ah, bl + npi * 2);
                }
            }
        }

        // row sums in-register + shfl over the 4 lanes of each row group
        float hb3v[32];
#pragma unroll
        for (int nt = 0; nt < 16; nt++) {
            float2 hv = *(float2*)(hb3s + nt * 8 + t2 * 2);
            hb3v[nt * 2] = hv.x; hb3v[nt * 2 + 1] = hv.y;
        }
        float p0a = 0.f, p1a = 0.f, p0b = 0.f, p1b = 0.f;
#pragma unroll
        for (int nt = 0; nt < 16; nt++) {
            p0a = fmaf(acc2[nt][0], acc2[nt][0], fmaf(acc2[nt][1], acc2[nt][1], p0a));
            p1a = fmaf(acc2[nt][0], hb3v[nt * 2], fmaf(acc2[nt][1], hb3v[nt * 2 + 1], p1a));
            p0b = fmaf(acc2[nt][2], acc2[nt][2], fmaf(acc2[nt][3], acc2[nt][3], p0b));
            p1b = fmaf(acc2[nt][2], hb3v[nt * 2], fmaf(acc2[nt][3], hb3v[nt * 2 + 1], p1b));
        }
#pragma unroll
        for (int o = 1; o <= 2; o <<= 1) {
            p0a += __shfl_xor_sync(0xffffffffu, p0a, o);
            p1a += __shfl_xor_sync(0xffffffffu, p1a, o);
            p0b += __shfl_xor_sync(0xffffffffu, p0b, o);
            p1b += __shfl_xor_sync(0xffffffffu, p1b, o);
        }

        // per-row epilogue 2 (each lane computes its 2 rows; redundant over 4 lanes)
        const int row1 = c * 16 + g2;
        const int row2 = row1 + 8;
        float cA1, cB1, cA2, cB2;
        {
            float un = un_s[row1];
            float mxn = fmaxf(sqrtf(p0a), MINN);
            float art = artanh_c(un);
            float t = tanhf(mxn / un * art);
            float g = t / mxn;
            float rn = t;
            if (rn > MAXN) { g *= MAXN / rn; rn = MAXN; }
            float xy = g * p1a;
            float x2 = rn * rn;
            float den = fmaxf(1.0f + 2.0f * xy + x2 * hb3sq, MINN);
            float A = (1.0f + 2.0f * xy + hb3sq) / den;
            float B = (1.0f - x2) / den;
            float nv = sqrtf(A * A * x2 + 2.0f * A * B * xy + B * B * hb3sq);
            float pf = (nv > MAXN) ? (MAXN / nv) : 1.0f;
            cA1 = pf * A * g; cB1 = pf * B;
        }
        {
            float un = un_s[row2];
            float mxn = fmaxf(sqrtf(p0b), MINN);
            float art = artanh_c(un);
            float t = tanhf(mxn / un * art);
            float g = t / mxn;
            float rn = t;
            if (rn > MAXN) { g *= MAXN / rn; rn = MAXN; }
            float xy = g * p1b;
            float x2 = rn * rn;
            float den = fmaxf(1.0f + 2.0f * xy + x2 * hb3sq, MINN);
            float A = (1.0f + 2.0f * xy + hb3sq) / den;
            float B = (1.0f - x2) / den;
            float nv = sqrtf(A * A * x2 + 2.0f * A * B * xy + B * B * hb3sq);
            float pf = (nv > MAXN) ? (MAXN / nv) : 1.0f;
            cA2 = pf * A * g; cB2 = pf * B;
        }

        // store straight from fragments
        {
            int g1r = baseRow + row1;
            int g2r = baseRow + row2;
            if (g1r < N) {
                float* o1 = out + (size_t)g1r * DOUT + t2 * 2;
#pragma unroll
                for (int nt = 0; nt < 16; nt++) {
                    float2 v;
                    v.x = cA1 * acc2[nt][0] + cB1 * hb3v[nt * 2];
                    v.y = cA1 * acc2[nt][1] + cB1 * hb3v[nt * 2 + 1];
                    *(float2*)(o1 + nt * 8) = v;
                }
            }
            if (g2r < N) {
                float* o2 = out + (size_t)g2r * DOUT + t2 * 2;
#pragma unroll
                for (int nt = 0; nt < 16; nt++) {
                    float2 v;
                    v.x = cA2 * acc2[nt][2] + cB2 * hb3v[nt * 2];
                    v.y = cA2 * acc2[nt][3] + cB2 * hb3v[nt * 2 + 1];
                    *(float2*)(o2 + nt * 8) = v;
                }
            }
        }
    }
}

extern "C" void kernel_launch(void* const* d_in, const int* in_sizes, int n_in,
                              void* d_out, int out_size) {
    const float* x  = (const float*)d_in[0];
    const float* W1 = (const float*)d_in[1];
    const float* b1 = (const float*)d_in[2];
    const float* W3 = (const float*)d_in[3];
    const float* b3 = (const float*)d_in[4];
    float* out = (float*)d_out;
    int N = in_sizes[0] / DIN;
    int nTiles = (N + MT - 1) / MT;
    int grid = nTiles < 296 ? nTiles : 296;

    cudaFuncSetAttribute(hnn_kernel, cudaFuncAttributeMaxDynamicSharedMemorySize, SMEM_BYTES);

    bias_kernel<<<1, 128>>>(b1, b3);
    prep_kernel<<<160, 256>>>(W1, W3);
    hnn_kernel<<<grid, TPB, SMEM_BYTES>>>(x, out, N, nTiles);
}

// round 7
// speedup vs baseline: 1.8765x; 1.0870x over previous
#include <cuda_runtime.h>
#include <cuda_bf16.h>
#include <math.h>
#include <stdint.h>

#define TPB   256
#define MT    128
#define DIN   512
#define HH    50
#define DOUT  128
#define MAXN  0.996f
#define MINN  1e-15f

typedef unsigned long long ull;
typedef uint32_t u32;

// ---- smem byte offsets ----
// X staging double buffer: buf b at OFF_X0H + b*36864 (hi), +18432 (lo)
#define OFF_X0H   0
#define OFF_X1H   36864
// W1 staging double buffer: buf b at OFF_W10H + b*18432 (hi), +9216 (lo)
#define OFF_W10H  73728
#define OFF_W11H  92160
// aliases (live after GEMM1 finishes):
#define OFF_MXS   0          // mx f32 [128][65] = 33280 <= 36864 (Xbuf0)
#define OFF_W3H   36864      // W3 hi 128x144 (Xbuf1 hi half)
#define OFF_W3L   55296      // W3 lo (Xbuf1 lo half)
#define OFF_UH    73728      // u hi 128x144 (W1 buf region)
#define OFF_UL    92160      // u lo 128x144
// persistent extras
#define OFF_HB1   110592     // 64 f32
#define OFF_HB3   110848     // 128 f32
#define OFF_X2S   111360     // 256 f32
#define OFF_UNS   112384     // 128 f32
#define SMEM_BYTES 112896

__device__ float g_hb1[64];
__device__ float g_hb3[128];
__device__ float g_hb1sq, g_hb3sq;
__device__ __align__(16) __nv_bfloat16 g_w1h[64 * 512];   // rows 50..63 zero
__device__ __align__(16) __nv_bfloat16 g_w1l[64 * 512];
__device__ __align__(16) __nv_bfloat16 g_w3h[128 * 64];   // k 50..63 zero
__device__ __align__(16) __nv_bfloat16 g_w3l[128 * 64];

__device__ __forceinline__ float artanh_c(float z) {
    z = fminf(z, 1.0f - 1e-7f);
    return 0.5f * logf((1.0f + z) / (1.0f - z));
}

// ---- HMMA / async helpers ----
__device__ __forceinline__ void mma_bf16(float* d, const u32* a, const u32* b) {
    asm("mma.sync.aligned.m16n8k16.row.col.f32.bf16.bf16.f32 "
        "{%0,%1,%2,%3}, {%4,%5,%6,%7}, {%8,%9}, {%0,%1,%2,%3};"
        : "+f"(d[0]), "+f"(d[1]), "+f"(d[2]), "+f"(d[3])
        : "r"(a[0]), "r"(a[1]), "r"(a[2]), "r"(a[3]), "r"(b[0]), "r"(b[1]));
}
__device__ __forceinline__ void ldsm4(u32* r, u32 addr) {
    asm volatile("ldmatrix.sync.aligned.m8n8.x4.shared.b16 {%0,%1,%2,%3}, [%4];"
        : "=r"(r[0]), "=r"(r[1]), "=r"(r[2]), "=r"(r[3]) : "r"(addr));
}
// truncation split of two floats -> packed bf16x2 hi (exact prefix) + bf16x2 lo
__device__ __forceinline__ void split2(float a, float b, u32& hi, u32& lo) {
    u32 ua = __float_as_uint(a), ub = __float_as_uint(b);
    u32 h;
    asm("prmt.b32 %0, %1, %2, 0x7632;" : "=r"(h) : "r"(ua), "r"(ub));
    float ha = __uint_as_float(ua & 0xFFFF0000u);
    float hb = __uint_as_float(ub & 0xFFFF0000u);
    float la = a - ha, lb = b - hb;
    u32 l;
    asm("cvt.rn.bf16x2.f32 %0, %1, %2;" : "=r"(l) : "f"(lb), "f"(la));
    hi = h; lo = l;
}
__device__ __forceinline__ void cp_async16(u32 sdst, const void* gsrc) {
    asm volatile("cp.async.ca.shared.global [%0], [%1], 16;" :: "r"(sdst), "l"(gsrc));
}
__device__ __forceinline__ void cp_wait_all() {
    asm volatile("cp.async.commit_group;\n\tcp.async.wait_group 0;" ::: "memory");
}

// setup 1: hyp_b = proj(expmap0(b)); also ||hyp_b||^2
__global__ void bias_kernel(const float* __restrict__ b1, const float* __restrict__ b3) {
    __shared__ float s[128];
    int t = threadIdx.x;

    float v1 = (t < HH) ? b1[t] : 0.0f;
    s[t] = v1 * v1;
    __syncthreads();
    for (int o = 64; o > 0; o >>= 1) { if (t < o) s[t] += s[t + o]; __syncthreads(); }
    float nb2 = s[0];
    __syncthreads();
    {
        float nb = fmaxf(sqrtf(nb2), MINN);
        float th = tanhf(nb);
        float sc = th / nb;
        if (th > MAXN) { sc *= MAXN / th; th = MAXN; }
        if (t < HH) g_hb1[t] = sc * v1;
        if (t == 0) g_hb1sq = th * th;
    }

    float v3 = b3[t];
    s[t] = v3 * v3;
    __syncthreads();
    for (int o = 64; o > 0; o >>= 1) { if (t < o) s[t] += s[t + o]; __syncthreads(); }
    nb2 = s[0];
    __syncthreads();
    {
        float nb = fmaxf(sqrtf(nb2), MINN);
        float th = tanhf(nb);
        float sc = th / nb;
        if (th > MAXN) { sc *= MAXN / th; th = MAXN; }
        g_hb3[t] = sc * v3;
        if (t == 0) g_hb3sq = th * th;
    }
}

// setup 2: W1 and W3 -> bf16 hi/lo (truncation split), zero-padded
__global__ void prep_kernel(const float* __restrict__ W1, const float* __restrict__ W3) {
    int idx = blockIdx.x * blockDim.x + threadIdx.x;
    if (idx < 64 * 512) {
        int row = idx >> 9;
        float v = (row < HH) ? W1[(size_t)row * DIN + (idx & 511)] : 0.0f;
        u32 uh = __float_as_uint(v) & 0xFFFF0000u;
        float hf = __uint_as_float(uh);
        g_w1h[idx] = __ushort_as_bfloat16((unsigned short)(uh >> 16));
        g_w1l[idx] = __float2bfloat16(v - hf);
    } else if (idx < 64 * 512 + 128 * 64) {
        int i = idx - 64 * 512;
        int n = i >> 6, k = i & 63;
        float v = (k < HH) ? W3[(size_t)n * HH + k] : 0.0f;
        u32 uh = __float_as_uint(v) & 0xFFFF0000u;
        float hf = __uint_as_float(uh);
        g_w3h[i] = __ushort_as_bfloat16((unsigned short)(uh >> 16));
        g_w3l[i] = __float2bfloat16(v - hf);
    }
}

extern __shared__ __align__(1024) char smraw[];

__global__ __launch_bounds__(TPB, 2)
void hnn_kernel(const float* __restrict__ X, float* __restrict__ out, int N, int nTiles)
{
    const u32 sb = (u32)__cvta_generic_to_shared(smraw);
    float* mxs  = (float*)(smraw + OFF_MXS);   // [row][j], stride 65
    float* hb1s = (float*)(smraw + OFF_HB1);
    float* hb3s = (float*)(smraw + OFF_HB3);
    float* x2s  = (float*)(smraw + OFF_X2S);
    float* un_s = (float*)(smraw + OFF_UNS);

    const int tid = threadIdx.x;
    const int lane = tid & 31;
    const int c = tid >> 5;           // warp id
    const int mg = c & 3;             // GEMM1 row group
    const int ng = c >> 2;            // GEMM1 col group

    for (int i = tid; i < 64; i += TPB) hb1s[i] = (i < HH) ? g_hb1[i] : 0.0f;
    if (tid < DOUT) hb3s[tid] = g_hb3[tid];
    const float hb1sq = g_hb1sq;
    const float hb3sq = g_hb3sq;

    // per-thread constants
    const int xrow = tid & 127;
    const int xkh  = tid >> 7;
    const u32 xoff = (u32)(xrow * 144 + xkh * 64);
    // GEMM1 ldmatrix lane components
    const u32 aRow = (u32)(mg * 32 + (lane & 15));
    const u32 aKof = (u32)((lane >> 4) * 16);
    const u32 bN   = (u32)(ng * 32 + ((lane >> 4) * 8) + (lane & 7));
    const u32 bKof = (u32)(((lane >> 3) & 1) * 16);
    // GEMM2 lane components
    const u32 a2H = sb + OFF_UH + (u32)((c * 16 + (lane & 15)) * 144 + (lane >> 4) * 16);
    const u32 a2L = a2H + 18432u;
    const u32 b2H = sb + OFF_W3H + (u32)((((lane >> 4) * 8) + (lane & 7)) * 144 + ((lane >> 3) & 1) * 16);
    const u32 b2L = b2H + 18432u;
    const int g2 = lane >> 2, t2 = lane & 3;

    // W1 cp.async addressing (buffer-relative dst)
    u32 w1_rel[4];
    const __nv_bfloat16* w1_gsrc[4];
#pragma unroll
    for (int p = 0; p < 4; p++) {
        int u = tid + 256 * p;
        int half = u >> 9, n = (u >> 3) & 63, j = u & 7;
        w1_rel[p] = (u32)(half * 9216 + n * 144 + j * 16);
        w1_gsrc[p] = (half ? g_w1l : g_w1h) + n * 512 + j * 8;
    }

    for (int tile = blockIdx.x; tile < nTiles; tile += gridDim.x) {
        const int baseRow = tile * MT;
        const int gr = baseRow + xrow;
        const bool valid = gr < N;
        const float* xptr = X + (size_t)gr * DIN + xkh * 32;
        float x2a = 0.0f;

        // prefetch x chunk 0 (register loads only)
        float4 xr[8];
#pragma unroll
        for (int q = 0; q < 8; q++)
            xr[q] = valid ? *(const float4*)(xptr + q * 4) : make_float4(0.f, 0.f, 0.f, 0.f);

        __syncthreads();   // prior tile's GEMM2 (U/W3 reads) done before staging overwrites

        float acc[2][4][4];
#pragma unroll
        for (int mt = 0; mt < 2; mt++)
#pragma unroll
            for (int nt = 0; nt < 4; nt++)
#pragma unroll
                for (int e = 0; e < 4; e++) acc[mt][nt][e] = 0.0f;

        // -------- GEMM1: x @ W1^T (HMMA bf16, 3-way split; double-buffered, 1 bar/chunk) ----
        for (int kc = 0; kc < 8; kc++) {
            const u32 bX = (u32)((kc & 1) ? OFF_X1H : OFF_X0H);
            const u32 bW = (u32)((kc & 1) ? OFF_W11H : OFF_W10H);

            // stage x chunk kc (truncation split)
#pragma unroll
            for (int q = 0; q < 8; q += 2) {
                float4 v0 = xr[q], v1 = xr[q + 1];
                u32 h0, h1, h2, h3, l0, l1, l2, l3;
                split2(v0.x, v0.y, h0, l0);
                split2(v0.z, v0.w, h1, l1);
                split2(v1.x, v1.y, h2, l2);
                split2(v1.z, v1.w, h3, l3);
                *(uint4*)(smraw + bX + xoff + q * 8) = make_uint4(h0, h1, h2, h3);
                *(uint4*)(smraw + bX + 18432 + xoff + q * 8) = make_uint4(l0, l1, l2, l3);
                x2a = fmaf(v0.x, v0.x, fmaf(v0.y, v0.y, fmaf(v0.z, v0.z, fmaf(v0.w, v0.w, x2a))));
                x2a = fmaf(v1.x, v1.x, fmaf(v1.y, v1.y, fmaf(v1.z, v1.z, fmaf(v1.w, v1.w, x2a))));
            }
            // W1 chunk kc via cp.async into buffer bW
#pragma unroll
            for (int p = 0; p < 4; p++)
                cp_async16(sb + bW + w1_rel[p], w1_gsrc[p] + kc * 64);

            // prefetch x chunk kc+1
            if (kc < 7) {
#pragma unroll
                for (int q = 0; q < 8; q++)
                    xr[q] = valid ? *(const float4*)(xptr + (kc + 1) * 64 + q * 4)
                                  : make_float4(0.f, 0.f, 0.f, 0.f);
            }
            cp_wait_all();
            __syncthreads();   // single barrier per chunk

            // MMAs over buffer kc
#pragma unroll
            for (int k16 = 0; k16 < 4; k16++) {
                u32 bh[8], bl[8];
#pragma unroll
                for (int np = 0; np < 2; np++) {
                    u32 boff = (bN + (u32)(np * 16)) * 144u + (u32)(k16 * 32) + bKof;
                    ldsm4(bh + np * 4, sb + bW + boff);
                    ldsm4(bl + np * 4, sb + bW + 9216 + boff);
                }
#pragma unroll
                for (int mt = 0; mt < 2; mt++) {
                    u32 aoff = (aRow + (u32)(mt * 16)) * 144u + (u32)(k16 * 32) + aKof;
                    u32 ah[4], al[4];
                    ldsm4(ah, sb + bX + aoff);
                    ldsm4(al, sb + bX + 18432 + aoff);
#pragma unroll
                    for (int nt = 0; nt < 4; nt++) {
                        mma_bf16(acc[mt][nt], ah, bh + nt * 2);
                        mma_bf16(acc[mt][nt], al, bh + nt * 2);
                        mma_bf16(acc[mt][nt], ah, bl + nt * 2);
                    }
                }
            }
        }

        // spill fragments to mxs [row][col] stride 65 (Xbuf0 alias; chunk-6 data dead)
        {
            int g = lane >> 2, t = lane & 3;
#pragma unroll
            for (int mt = 0; mt < 2; mt++) {
                int r0 = mg * 32 + mt * 16 + g;
#pragma unroll
                for (int nt = 0; nt < 4; nt++) {
                    int col = ng * 32 + nt * 8 + t * 2;
                    mxs[r0 * 65 + col]           = acc[mt][nt][0];
                    mxs[r0 * 65 + col + 1]       = acc[mt][nt][1];
                    mxs[(r0 + 8) * 65 + col]     = acc[mt][nt][2];
                    mxs[(r0 + 8) * 65 + col + 1] = acc[mt][nt][3];
                }
            }
        }
        x2s[xkh * 128 + xrow] = x2a;
        __syncthreads();   // all MMAs + spills done; Xbuf1 / W1 bufs now free

        // stage W3 hi/lo into Xbuf1 alias (hidden under epilogue 1)
        for (int i = tid; i < 1024; i += TPB) {
            int n = i >> 3, j = i & 7;
            cp_async16(sb + OFF_W3H + (u32)(n * 144 + j * 16), g_w3h + n * 64 + j * 8);
            cp_async16(sb + OFF_W3L + (u32)(n * 144 + j * 16), g_w3l + n * 64 + j * 8);
        }

        // -------- Epilogue 1 (threads 0..127, one per row) --------
        if (tid < 128) {
            const int r0 = tid;
            float sx2 = x2s[r0] + x2s[128 + r0];
            float nx = fmaxf(sqrtf(sx2), MINN);
            float th = tanhf(nx);
            float al = th / nx;
            float xn1 = fmaxf(th, MINN);

            float p0 = 0.f, p1 = 0.f;
#pragma unroll
            for (int j = 0; j < HH; j++) {
                float v = al * mxs[r0 * 65 + j];
                p0 = fmaf(v, v, p0);
                p1 = fmaf(v, hb1s[j], p1);
            }
            float mxn = fmaxf(sqrtf(p0), MINN);
            float art = artanh_c(xn1);
            float t = tanhf(mxn / xn1 * art);
            float g = t / mxn;
            float rn = t;
            if (rn > MAXN) { g *= MAXN / rn; rn = MAXN; }
            float xy = g * p1;
            float x2 = rn * rn;
            float den = fmaxf(1.0f + 2.0f * xy + x2 * hb1sq, MINN);
            float A = (1.0f + 2.0f * xy + hb1sq) / den;
            float B = (1.0f - x2) / den;
            float nv2 = A * A * x2 + 2.0f * A * B * xy + B * B * hb1sq;
            float nv = sqrtf(nv2);
            float pf = (nv > MAXN) ? (MAXN / nv) : 1.0f;
            nv = fminf(nv, MAXN);
            float beta = artanh_c(nv) / fmaxf(nv, MINN);
            float C1a = beta * pf * A * g * al;
            float C2 = beta * pf * B;

            float xt_buf[HH];
            float p = 0.f;
#pragma unroll
            for (int j = 0; j < HH; j++) {
                float xt = C1a * mxs[r0 * 65 + j] + C2 * hb1s[j];
                xt = (xt > 0.0f) ? xt : 0.01f * xt;
                xt_buf[j] = xt;
                p = fmaf(xt, xt, p);
            }
            float nxt = fmaxf(sqrtf(p), MINN);
            float t3 = tanhf(nxt);
            float gam = t3 / nxt;
            if (t3 > MAXN) { gam *= MAXN / t3; t3 = MAXN; }
            un_s[r0] = fmaxf(t3, MINN);

            // u as bf16 hi/lo into ldmatrix layout (k padded to 64 with zeros)
#pragma unroll
            for (int jj = 0; jj < 25; jj++) {
                float v0 = gam * xt_buf[jj * 2];
                float v1 = (jj * 2 + 1 < HH) ? gam * xt_buf[jj * 2 + 1] : 0.0f;
                u32 h, l;
                split2(v0, v1, h, l);
                *(u32*)(smraw + OFF_UH + r0 * 144 + jj * 4) = h;
                *(u32*)(smraw + OFF_UL + r0 * 144 + jj * 4) = l;
            }
#pragma unroll
            for (int jj = 25; jj < 32; jj++) {
                *(u32*)(smraw + OFF_UH + r0 * 144 + jj * 4) = 0u;
                *(u32*)(smraw + OFF_UL + r0 * 144 + jj * 4) = 0u;
            }
        }
        cp_wait_all();
        __syncthreads();

        // -------- GEMM2: u @ W3^T (HMMA bf16, 3-way split; 16 rows/warp) --------
        float acc2[16][4];
#pragma unroll
        for (int nt = 0; nt < 16; nt++)
#pragma unroll
            for (int e = 0; e < 4; e++) acc2[nt][e] = 0.0f;

#pragma unroll
        for (int k16 = 0; k16 < 4; k16++) {
            u32 ah[4], al[4];
            ldsm4(ah, a2H + (u32)(k16 * 32));
            ldsm4(al, a2L + (u32)(k16 * 32));
#pragma unroll
            for (int np = 0; np < 8; np++) {
                u32 bh[4], bl[4];
                u32 boff = (u32)(np * 2304 + k16 * 32);
                ldsm4(bh, b2H + boff);
                ldsm4(bl, b2L + boff);
#pragma unroll
                for (int npi = 0; npi < 2; npi++) {
                    mma_bf16(acc2[np * 2 + npi], ah, bh + npi * 2);
                    mma_bf16(acc2[np * 2 + npi], al, bh + npi * 2);
                    mma_bf16(acc2[np * 2 + npi], ah, bl + npi * 2);
                }
            }
        }

        // row sums in-register + shfl over the 4 lanes of each row group
        float hb3v[32];
#pragma unroll
        for (int nt = 0; nt < 16; nt++) {
            float2 hv = *(float2*)(hb3s + nt * 8 + t2 * 2);
            hb3v[nt * 2] = hv.x; hb3v[nt * 2 + 1] = hv.y;
        }
        float p0a = 0.f, p1a = 0.f, p0b = 0.f, p1b = 0.f;
#pragma unroll
        for (int nt = 0; nt < 16; nt++) {
            p0a = fmaf(acc2[nt][0], acc2[nt][0], fmaf(acc2[nt][1], acc2[nt][1], p0a));
            p1a = fmaf(acc2[nt][0], hb3v[nt * 2], fmaf(acc2[nt][1], hb3v[nt * 2 + 1], p1a));
            p0b = fmaf(acc2[nt][2], acc2[nt][2], fmaf(acc2[nt][3], acc2[nt][3], p0b));
            p1b = fmaf(acc2[nt][2], hb3v[nt * 2], fmaf(acc2[nt][3], hb3v[nt * 2 + 1], p1b));
        }
#pragma unroll
        for (int o = 1; o <= 2; o <<= 1) {
            p0a += __shfl_xor_sync(0xffffffffu, p0a, o);
            p1a += __shfl_xor_sync(0xffffffffu, p1a, o);
            p0b += __shfl_xor_sync(0xffffffffu, p0b, o);
            p1b += __shfl_xor_sync(0xffffffffu, p1b, o);
        }

        // per-row epilogue 2
        const int row1 = c * 16 + g2;
        const int row2 = row1 + 8;
        float cA1, cB1, cA2, cB2;
        {
            float un = un_s[row1];
            float mxn = fmaxf(sqrtf(p0a), MINN);
            float art = artanh_c(un);
            float t = tanhf(mxn / un * art);
            float g = t / mxn;
            float rn = t;
            if (rn > MAXN) { g *= MAXN / rn; rn = MAXN; }
            float xy = g * p1a;
            float x2 = rn * rn;
            float den = fmaxf(1.0f + 2.0f * xy + x2 * hb3sq, MINN);
            float A = (1.0f + 2.0f * xy + hb3sq) / den;
            float B = (1.0f - x2) / den;
            float nv = sqrtf(A * A * x2 + 2.0f * A * B * xy + B * B * hb3sq);
            float pf = (nv > MAXN) ? (MAXN / nv) : 1.0f;
            cA1 = pf * A * g; cB1 = pf * B;
        }
        {
            float un = un_s[row2];
            float mxn = fmaxf(sqrtf(p0b), MINN);
            float art = artanh_c(un);
            float t = tanhf(mxn / un * art);
            float g = t / mxn;
            float rn = t;
            if (rn > MAXN) { g *= MAXN / rn; rn = MAXN; }
            float xy = g * p1b;
            float x2 = rn * rn;
            float den = fmaxf(1.0f + 2.0f * xy + x2 * hb3sq, MINN);
            float A = (1.0f + 2.0f * xy + hb3sq) / den;
            float B = (1.0f - x2) / den;
            float nv = sqrtf(A * A * x2 + 2.0f * A * B * xy + B * B * hb3sq);
            float pf = (nv > MAXN) ? (MAXN / nv) : 1.0f;
            cA2 = pf * A * g; cB2 = pf * B;
        }

        // store straight from fragments
        {
            int g1r = baseRow + row1;
            int g2r = baseRow + row2;
            if (g1r < N) {
                float* o1 = out + (size_t)g1r * DOUT + t2 * 2;
#pragma unroll
                for (int nt = 0; nt < 16; nt++) {
                    float2 v;
                    v.x = cA1 * acc2[nt][0] + cB1 * hb3v[nt * 2];
                    v.y = cA1 * acc2[nt][1] + cB1 * hb3v[nt * 2 + 1];
                    *(float2*)(o1 + nt * 8) = v;
                }
            }
            if (g2r < N) {
                float* o2 = out + (size_t)g2r * DOUT + t2 * 2;
#pragma unroll
                for (int nt = 0; nt < 16; nt++) {
                    float2 v;
                    v.x = cA2 * acc2[nt][2] + cB2 * hb3v[nt * 2];
                    v.y = cA2 * acc2[nt][3] + cB2 * hb3v[nt * 2 + 1];
                    *(float2*)(o2 + nt * 8) = v;
                }
            }
        }
    }
}

extern "C" void kernel_launch(void* const* d_in, const int* in_sizes, int n_in,
                              void* d_out, int out_size) {
    const float* x  = (const float*)d_in[0];
    const float* W1 = (const float*)d_in[1];
    const float* b1 = (const float*)d_in[2];
    const float* W3 = (const float*)d_in[3];
    const float* b3 = (const float*)d_in[4];
    float* out = (float*)d_out;
    int N = in_sizes[0] / DIN;
    int nTiles = (N + MT - 1) / MT;
    int grid = nTiles < 296 ? nTiles : 296;

    cudaFuncSetAttribute(hnn_kernel, cudaFuncAttributeMaxDynamicSharedMemorySize, SMEM_BYTES);

    bias_kernel<<<1, 128>>>(b1, b3);
    prep_kernel<<<160, 256>>>(W1, W3);
    hnn_kernel<<<grid, TPB, SMEM_BYTES>>>(x, out, N, nTiles);
}